// round 3
// baseline (speedup 1.0000x reference)
#include <cuda_runtime.h>
#include <cstddef>

#define B_   32
#define T_   14
#define M_   2048
#define QD   768
#define KVD  1024
#define H_   12
#define HD_  64
#define FF_  3072
#define BT   (B_*T_)      // 448
#define R_   (B_*M_)      // 65536
#define EPS_ 1e-5f

// ---------------- scratch (device globals; no allocation allowed) ----------------
__device__ float g_Q[BT*QD];        // 1.4 MB
__device__ float g_K[(size_t)R_*QD];// 201 MB
__device__ float g_V[(size_t)R_*QD];// 201 MB
__device__ float g_attn[BT*QD];
__device__ float g_x1[BT*QD];
__device__ float g_h[BT*FF_];       // 5.5 MB
__device__ float g_ff[BT*QD];

// ---------------- Q projection: per-expert-token weight matrices ----------------
// grid (BT, QD/128), block 128. Q[bt, col] = x[bt,:] . WQ[t][:,col] + bQ[t,col]
__global__ __launch_bounds__(128) void qproj_kernel(
    const float* __restrict__ X, const float* __restrict__ WQ,
    const float* __restrict__ bQ, float* __restrict__ Q)
{
    int bt  = blockIdx.x;
    int t   = bt % T_;
    int col = blockIdx.y * 128 + threadIdx.x;
    __shared__ float xs[QD];
    for (int i = threadIdx.x; i < QD; i += 128) xs[i] = X[(size_t)bt*QD + i];
    __syncthreads();
    const float* W = WQ + (size_t)t * QD * QD;
    float acc = bQ[t*QD + col];
    #pragma unroll 8
    for (int e = 0; e < QD; e++) acc += xs[e] * W[(size_t)e*QD + col];
    Q[(size_t)bt*QD + col] = acc;
}

// ---------------- fused K/V projection GEMM ----------------
// X [R_, KVD] x WK/WV [KVD, QD] -> K,V [R_, QD]. Tiles: 128x64, BK=32, 256 thr.
__global__ __launch_bounds__(256) void kvproj_kernel(
    const float* __restrict__ X,
    const float* __restrict__ WK, const float* __restrict__ bK,
    const float* __restrict__ WV, const float* __restrict__ bV,
    float* __restrict__ Kout, float* __restrict__ Vout)
{
    __shared__ float As[128][33];
    __shared__ float Bk[32][64];
    __shared__ float Bv[32][64];
    int tid = threadIdx.x;
    int rowBase = blockIdx.x * 128;
    int colBase = blockIdx.y * 64;
    int tx = tid & 15, ty = tid >> 4;
    int row0 = ty * 8, col0 = tx * 4;
    float accK[8][4], accV[8][4];
    #pragma unroll
    for (int i = 0; i < 8; i++)
        #pragma unroll
        for (int j = 0; j < 4; j++) { accK[i][j] = 0.f; accV[i][j] = 0.f; }

    for (int k0 = 0; k0 < KVD; k0 += 32) {
        #pragma unroll
        for (int i = 0; i < 16; i++) {
            int idx = tid + i * 256;
            int r = idx >> 5, c = idx & 31;
            As[r][c] = X[(size_t)(rowBase + r) * KVD + k0 + c];
        }
        #pragma unroll
        for (int i = 0; i < 8; i++) {
            int idx = tid + i * 256;
            int r = idx >> 6, c = idx & 63;
            Bk[r][c] = WK[(size_t)(k0 + r) * QD + colBase + c];
            Bv[r][c] = WV[(size_t)(k0 + r) * QD + colBase + c];
        }
        __syncthreads();
        #pragma unroll
        for (int kk = 0; kk < 32; kk++) {
            float a[8], b0[4], b1[4];
            #pragma unroll
            for (int i = 0; i < 8; i++) a[i] = As[row0 + i][kk];
            #pragma unroll
            for (int j = 0; j < 4; j++) { b0[j] = Bk[kk][col0 + j]; b1[j] = Bv[kk][col0 + j]; }
            #pragma unroll
            for (int i = 0; i < 8; i++)
                #pragma unroll
                for (int j = 0; j < 4; j++) {
                    accK[i][j] += a[i] * b0[j];
                    accV[i][j] += a[i] * b1[j];
                }
        }
        __syncthreads();
    }
    #pragma unroll
    for (int i = 0; i < 8; i++) {
        int r = rowBase + row0 + i;
        #pragma unroll
        for (int j = 0; j < 4; j++) {
            int c = colBase + col0 + j;
            Kout[(size_t)r*QD + c] = accK[i][j] + bK[c];
            Vout[(size_t)r*QD + c] = accV[i][j] + bV[c];
        }
    }
}

// ---------------- generic GEMM with bias (+optional ReLU), M-guarded ----------------
template<bool RELU>
__global__ __launch_bounds__(256) void gemm_bias_kernel(
    const float* __restrict__ A, const float* __restrict__ W,
    const float* __restrict__ bias, float* __restrict__ C,
    int Mr, int Nc, int Kd)
{
    __shared__ float As[128][33];
    __shared__ float Bs[32][64];
    int tid = threadIdx.x;
    int rowBase = blockIdx.x * 128;
    int colBase = blockIdx.y * 64;
    int tx = tid & 15, ty = tid >> 4;
    int row0 = ty * 8, col0 = tx * 4;
    float acc[8][4];
    #pragma unroll
    for (int i = 0; i < 8; i++)
        #pragma unroll
        for (int j = 0; j < 4; j++) acc[i][j] = 0.f;

    for (int k0 = 0; k0 < Kd; k0 += 32) {
        #pragma unroll
        for (int i = 0; i < 16; i++) {
            int idx = tid + i * 256;
            int r = idx >> 5, c = idx & 31;
            int gr = rowBase + r;
            As[r][c] = (gr < Mr) ? A[(size_t)gr * Kd + k0 + c] : 0.f;
        }
        #pragma unroll
        for (int i = 0; i < 8; i++) {
            int idx = tid + i * 256;
            int r = idx >> 6, c = idx & 63;
            Bs[r][c] = W[(size_t)(k0 + r) * Nc + colBase + c];
        }
        __syncthreads();
        #pragma unroll
        for (int kk = 0; kk < 32; kk++) {
            float a[8], b0[4];
            #pragma unroll
            for (int i = 0; i < 8; i++) a[i] = As[row0 + i][kk];
            #pragma unroll
            for (int j = 0; j < 4; j++) b0[j] = Bs[kk][col0 + j];
            #pragma unroll
            for (int i = 0; i < 8; i++)
                #pragma unroll
                for (int j = 0; j < 4; j++) acc[i][j] += a[i] * b0[j];
        }
        __syncthreads();
    }
    #pragma unroll
    for (int i = 0; i < 8; i++) {
        int r = rowBase + row0 + i;
        if (r < Mr) {
            #pragma unroll
            for (int j = 0; j < 4; j++) {
                int c = colBase + col0 + j;
                float v = acc[i][j] + bias[c];
                if (RELU) v = fmaxf(v, 0.f);
                C[(size_t)r*Nc + c] = v;
            }
        }
    }
}

// ---------------- attention: one block per (b,h) ----------------
// dyn smem: Ss[T_*M_] + Qs[T_*HD_] + Vs[128*HD_]
__global__ __launch_bounds__(256) void attn_kernel(
    const float* __restrict__ Q, const float* __restrict__ Kd,
    const float* __restrict__ Vd, float* __restrict__ attnw,
    float* __restrict__ attn_out)
{
    extern __shared__ float sm[];
    float* Ss = sm;                    // T_*M_
    float* Qs = Ss + T_*M_;            // T_*HD_
    float* Vs = Qs + T_*HD_;           // 128*HD_
    __shared__ float red[256];
    int tid = threadIdx.x;
    int b = blockIdx.x / H_, h = blockIdx.x % H_;

    for (int i = tid; i < T_*HD_; i += 256) {
        int t = i >> 6, d = i & 63;
        Qs[i] = Q[(size_t)(b*T_ + t)*QD + h*HD_ + d];
    }
    __syncthreads();

    // scores
    for (int m = tid; m < M_; m += 256) {
        float acc[T_];
        #pragma unroll
        for (int t = 0; t < T_; t++) acc[t] = 0.f;
        const float* kp = Kd + (size_t)(b*M_ + m)*QD + h*HD_;
        #pragma unroll 4
        for (int d = 0; d < HD_; d++) {
            float kv = kp[d];
            #pragma unroll
            for (int t = 0; t < T_; t++) acc[t] += Qs[t*HD_ + d] * kv;
        }
        #pragma unroll
        for (int t = 0; t < T_; t++) Ss[t*M_ + m] = acc[t] * 0.125f;
    }
    __syncthreads();

    // softmax per row, write attn_w
    for (int t = 0; t < T_; t++) {
        float mx = -1e30f;
        for (int m = tid; m < M_; m += 256) mx = fmaxf(mx, Ss[t*M_ + m]);
        red[tid] = mx; __syncthreads();
        for (int s = 128; s > 0; s >>= 1) {
            if (tid < s) red[tid] = fmaxf(red[tid], red[tid + s]);
            __syncthreads();
        }
        mx = red[0]; __syncthreads();
        float sum = 0.f;
        for (int m = tid; m < M_; m += 256) {
            float e = __expf(Ss[t*M_ + m] - mx);
            Ss[t*M_ + m] = e;
            sum += e;
        }
        red[tid] = sum; __syncthreads();
        for (int s = 128; s > 0; s >>= 1) {
            if (tid < s) red[tid] += red[tid + s];
            __syncthreads();
        }
        float inv = 1.f / red[0]; __syncthreads();
        for (int m = tid; m < M_; m += 256) {
            float p = Ss[t*M_ + m] * inv;
            Ss[t*M_ + m] = p;
            attnw[((size_t)(b*T_ + t)*H_ + h)*M_ + m] = p;
        }
        __syncthreads();
    }

    // attn_out = P @ V
    int d = tid & 63, t0 = tid >> 6;   // t0: 0..3; thread owns t = t0+4j
    float acc4[4] = {0.f, 0.f, 0.f, 0.f};
    for (int m0 = 0; m0 < M_; m0 += 128) {
        for (int i = tid; i < 128*64; i += 256) {
            int r = i >> 6, c = i & 63;
            Vs[i] = Vd[(size_t)(b*M_ + m0 + r)*QD + h*HD_ + c];
        }
        __syncthreads();
        for (int m = 0; m < 128; m++) {
            float v = Vs[m*64 + d];
            #pragma unroll
            for (int j = 0; j < 4; j++) {
                int t = t0 + 4*j;
                float w = (t < T_) ? Ss[t*M_ + m0 + m] : 0.f;
                acc4[j] += w * v;
            }
        }
        __syncthreads();
    }
    #pragma unroll
    for (int j = 0; j < 4; j++) {
        int t = t0 + 4*j;
        if (t < T_) attn_out[(size_t)(b*T_ + t)*QD + h*HD_ + d] = acc4[j];
    }
}

// ---------------- residual add + LayerNorm ----------------
__global__ __launch_bounds__(256) void add_ln_kernel(
    const float* __restrict__ A, const float* __restrict__ Bv,
    const float* __restrict__ g, const float* __restrict__ be,
    float* __restrict__ out)
{
    __shared__ float xs[QD];
    __shared__ float red[256];
    int r = blockIdx.x, tid = threadIdx.x;
    float lsum = 0.f;
    for (int i = tid; i < QD; i += 256) {
        float v = A[(size_t)r*QD + i] + Bv[(size_t)r*QD + i];
        xs[i] = v;
        lsum += v;
    }
    red[tid] = lsum; __syncthreads();
    for (int s = 128; s > 0; s >>= 1) {
        if (tid < s) red[tid] += red[tid + s];
        __syncthreads();
    }
    float mu = red[0] / QD; __syncthreads();
    float lv = 0.f;
    for (int i = tid; i < QD; i += 256) {
        float d0 = xs[i] - mu;
        lv += d0 * d0;
    }
    red[tid] = lv; __syncthreads();
    for (int s = 128; s > 0; s >>= 1) {
        if (tid < s) red[tid] += red[tid + s];
        __syncthreads();
    }
    float inv = rsqrtf(red[0] / QD + EPS_); __syncthreads();
    for (int i = tid; i < QD; i += 256)
        out[(size_t)r*QD + i] = (xs[i] - mu) * inv * g[i] + be[i];
}

// ---------------- launch ----------------
extern "C" void kernel_launch(void* const* d_in, const int* in_sizes, int n_in,
                              void* d_out, int out_size)
{
    const float* X   = (const float*)d_in[0];   // expert_tokens [B,T,QD]
    const float* KV  = (const float*)d_in[1];   // key_value_embeddings [B,M,KVD]
    const float* WQ  = (const float*)d_in[2];
    const float* bQ  = (const float*)d_in[3];
    const float* WK  = (const float*)d_in[4];
    const float* bK  = (const float*)d_in[5];
    const float* WV  = (const float*)d_in[6];
    const float* bV  = (const float*)d_in[7];
    const float* W1  = (const float*)d_in[8];
    const float* b1  = (const float*)d_in[9];
    const float* W2  = (const float*)d_in[10];
    const float* b2  = (const float*)d_in[11];
    const float* g1  = (const float*)d_in[12];
    const float* be1 = (const float*)d_in[13];
    const float* g2  = (const float*)d_in[14];
    const float* be2 = (const float*)d_in[15];

    float* out   = (float*)d_out;              // [BT, QD]
    float* attnw = out + (size_t)BT*QD;        // [B,T,H,M]

    float *Qp, *Kp, *Vp, *Ap, *X1, *Hm, *Fp;
    cudaGetSymbolAddress((void**)&Qp, g_Q);
    cudaGetSymbolAddress((void**)&Kp, g_K);
    cudaGetSymbolAddress((void**)&Vp, g_V);
    cudaGetSymbolAddress((void**)&Ap, g_attn);
    cudaGetSymbolAddress((void**)&X1, g_x1);
    cudaGetSymbolAddress((void**)&Hm, g_h);
    cudaGetSymbolAddress((void**)&Fp, g_ff);

    // Q projection
    qproj_kernel<<<dim3(BT, QD/128), 128>>>(X, WQ, bQ, Qp);

    // K/V projection (dominant GEMM)
    kvproj_kernel<<<dim3(R_/128, QD/64), 256>>>(KV, WK, bK, WV, bV, Kp, Vp);

    // attention
    const int SMEM_ATTN = (T_*M_ + T_*HD_ + 128*HD_) * (int)sizeof(float); // 151040
    cudaFuncSetAttribute(attn_kernel, cudaFuncAttributeMaxDynamicSharedMemorySize, SMEM_ATTN);
    attn_kernel<<<B_*H_, 256, SMEM_ATTN>>>(Qp, Kp, Vp, attnw, Ap);

    // x1 = LN(tokens + attn_out)
    add_ln_kernel<<<BT, 256>>>(X, Ap, g1, be1, X1);

    // FFN
    gemm_bias_kernel<true ><<<dim3((BT+127)/128, FF_/64), 256>>>(X1, W1, b1, Hm, BT, FF_, QD);
    gemm_bias_kernel<false><<<dim3((BT+127)/128, QD/64), 256>>>(Hm, W2, b2, Fp, BT, QD, FF_);

    // out = LN(x1 + ff)
    add_ln_kernel<<<BT, 256>>>(X1, Fp, g2, be2, out);
}

// round 4
// speedup vs baseline: 2.3087x; 2.3087x over previous
#include <cuda_runtime.h>
#include <cstdint>
#include <cstddef>

#define B_   32
#define T_   14
#define M_   2048
#define QD   768
#define KVD  1024
#define H_   12
#define HD_  64
#define FF_  3072
#define BT   (B_*T_)      // 448
#define R_   (B_*M_)      // 65536
#define EPS_ 1e-5f

// ---------------- scratch (device globals; no allocation allowed) ----------------
__device__ float g_Q[BT*QD];
__device__ float g_K[(size_t)R_*QD];
__device__ float g_V[(size_t)R_*QD];
__device__ float g_attn[BT*QD];
__device__ float g_x1[BT*QD];
__device__ float g_h[BT*FF_];
__device__ float g_ff[BT*QD];

// ---------------- helpers ----------------
__device__ __forceinline__ uint32_t f2tf32(float x) {
    uint32_t r;
    asm("cvt.rna.tf32.f32 %0, %1;" : "=r"(r) : "f"(x));
    return r;
}

__device__ __forceinline__ void mma_tf32(float* c, const uint32_t* a, uint32_t b0, uint32_t b1) {
    asm volatile(
        "mma.sync.aligned.m16n8k8.row.col.f32.tf32.tf32.f32 "
        "{%0,%1,%2,%3}, {%4,%5,%6,%7}, {%8,%9}, {%0,%1,%2,%3};\n"
        : "+f"(c[0]), "+f"(c[1]), "+f"(c[2]), "+f"(c[3])
        : "r"(a[0]), "r"(a[1]), "r"(a[2]), "r"(a[3]), "r"(b0), "r"(b1));
}

// ---------------- Q projection: per-expert-token weight matrices ----------------
__global__ __launch_bounds__(128) void qproj_kernel(
    const float* __restrict__ X, const float* __restrict__ WQ,
    const float* __restrict__ bQ, float* __restrict__ Q)
{
    int bt  = blockIdx.x;
    int t   = bt % T_;
    int col = blockIdx.y * 128 + threadIdx.x;
    __shared__ float xs[QD];
    for (int i = threadIdx.x; i < QD; i += 128) xs[i] = X[(size_t)bt*QD + i];
    __syncthreads();
    const float* W = WQ + (size_t)t * QD * QD;
    float acc = bQ[t*QD + col];
    #pragma unroll 8
    for (int e = 0; e < QD; e++) acc += xs[e] * W[(size_t)e*QD + col];
    Q[(size_t)bt*QD + col] = acc;
}

// ---------------- fused K/V projection GEMM (tf32 tensor cores) ----------------
// X [R_, KVD] x WK/WV [KVD, QD] -> K,V [R_, QD].
// Block tile 128x64, 256 threads = 8 warps (4 along M x 2 along N), warp tile m32n32.
__global__ __launch_bounds__(256, 2) void kvproj_tc_kernel(
    const float* __restrict__ X,
    const float* __restrict__ WK, const float* __restrict__ bK,
    const float* __restrict__ WV, const float* __restrict__ bV,
    float* __restrict__ Kout, float* __restrict__ Vout)
{
    // pads chosen for conflict-free fragment loads:
    // As stride 36 -> bank = (4r + c) % 32 distinct over a-frag lanes
    // B  stride 72 -> bank = (8k + n) % 32 distinct over b-frag lanes
    __shared__ uint32_t As[128][36];
    __shared__ uint32_t Bks[32][72];
    __shared__ uint32_t Bvs[32][72];

    int tid  = threadIdx.x;
    int lane = tid & 31;
    int w    = tid >> 5;
    int warpM = w & 3;   // 0..3
    int warpN = w >> 2;  // 0..1
    int rowBase = blockIdx.x * 128;
    int colBase = blockIdx.y * 64;

    float accK[2][4][4], accV[2][4][4];
    #pragma unroll
    for (int mi = 0; mi < 2; mi++)
        #pragma unroll
        for (int ni = 0; ni < 4; ni++)
            #pragma unroll
            for (int q = 0; q < 4; q++) { accK[mi][ni][q] = 0.f; accV[mi][ni][q] = 0.f; }

    int lg = lane >> 2;       // group id
    int lt = lane & 3;        // thread-in-group

    for (int k0 = 0; k0 < KVD; k0 += 32) {
        // load X tile 128x32 (1024 float4, 4 per thread), convert to tf32
        #pragma unroll
        for (int i = 0; i < 4; i++) {
            int idx = tid + i * 256;
            int r  = idx >> 3;
            int c4 = (idx & 7) << 2;
            float4 v = *(const float4*)&X[(size_t)(rowBase + r) * KVD + k0 + c4];
            As[r][c4 + 0] = f2tf32(v.x);
            As[r][c4 + 1] = f2tf32(v.y);
            As[r][c4 + 2] = f2tf32(v.z);
            As[r][c4 + 3] = f2tf32(v.w);
        }
        // load WK/WV tiles 32x64 (512 float4 each, 2 per thread)
        #pragma unroll
        for (int i = 0; i < 2; i++) {
            int idx = tid + i * 256;
            int r  = idx >> 4;
            int c4 = (idx & 15) << 2;
            float4 vk = *(const float4*)&WK[(size_t)(k0 + r) * QD + colBase + c4];
            float4 vv = *(const float4*)&WV[(size_t)(k0 + r) * QD + colBase + c4];
            Bks[r][c4 + 0] = f2tf32(vk.x);
            Bks[r][c4 + 1] = f2tf32(vk.y);
            Bks[r][c4 + 2] = f2tf32(vk.z);
            Bks[r][c4 + 3] = f2tf32(vk.w);
            Bvs[r][c4 + 0] = f2tf32(vv.x);
            Bvs[r][c4 + 1] = f2tf32(vv.y);
            Bvs[r][c4 + 2] = f2tf32(vv.z);
            Bvs[r][c4 + 3] = f2tf32(vv.w);
        }
        __syncthreads();

        #pragma unroll
        for (int ks = 0; ks < 4; ks++) {
            int kb = ks * 8;
            uint32_t a[2][4];
            #pragma unroll
            for (int mi = 0; mi < 2; mi++) {
                int r = warpM * 32 + mi * 16 + lg;
                int c = kb + lt;
                a[mi][0] = As[r][c];
                a[mi][1] = As[r + 8][c];
                a[mi][2] = As[r][c + 4];
                a[mi][3] = As[r + 8][c + 4];
            }
            #pragma unroll
            for (int ni = 0; ni < 4; ni++) {
                int n  = warpN * 32 + ni * 8 + lg;
                int kr = kb + lt;
                uint32_t bk0 = Bks[kr][n], bk1 = Bks[kr + 4][n];
                uint32_t bv0 = Bvs[kr][n], bv1 = Bvs[kr + 4][n];
                #pragma unroll
                for (int mi = 0; mi < 2; mi++) {
                    mma_tf32(accK[mi][ni], a[mi], bk0, bk1);
                    mma_tf32(accV[mi][ni], a[mi], bv0, bv1);
                }
            }
        }
        __syncthreads();
    }

    // epilogue: bias + store (float2 per fragment row)
    #pragma unroll
    for (int mi = 0; mi < 2; mi++) {
        #pragma unroll
        for (int ni = 0; ni < 4; ni++) {
            int r = rowBase + warpM * 32 + mi * 16 + lg;
            int c = colBase + warpN * 32 + ni * 8 + lt * 2;
            float bk0 = bK[c], bk1 = bK[c + 1];
            float bv0 = bV[c], bv1 = bV[c + 1];
            float2 v;
            v.x = accK[mi][ni][0] + bk0; v.y = accK[mi][ni][1] + bk1;
            *(float2*)&Kout[(size_t)r * QD + c] = v;
            v.x = accK[mi][ni][2] + bk0; v.y = accK[mi][ni][3] + bk1;
            *(float2*)&Kout[(size_t)(r + 8) * QD + c] = v;
            v.x = accV[mi][ni][0] + bv0; v.y = accV[mi][ni][1] + bv1;
            *(float2*)&Vout[(size_t)r * QD + c] = v;
            v.x = accV[mi][ni][2] + bv0; v.y = accV[mi][ni][3] + bv1;
            *(float2*)&Vout[(size_t)(r + 8) * QD + c] = v;
        }
    }
}

// ---------------- generic GEMM with bias (+optional ReLU), M-guarded ----------------
template<bool RELU>
__global__ __launch_bounds__(256) void gemm_bias_kernel(
    const float* __restrict__ A, const float* __restrict__ W,
    const float* __restrict__ bias, float* __restrict__ C,
    int Mr, int Nc, int Kd)
{
    __shared__ float As[128][33];
    __shared__ float Bs[32][64];
    int tid = threadIdx.x;
    int rowBase = blockIdx.x * 128;
    int colBase = blockIdx.y * 64;
    int tx = tid & 15, ty = tid >> 4;
    int row0 = ty * 8, col0 = tx * 4;
    float acc[8][4];
    #pragma unroll
    for (int i = 0; i < 8; i++)
        #pragma unroll
        for (int j = 0; j < 4; j++) acc[i][j] = 0.f;

    for (int k0 = 0; k0 < Kd; k0 += 32) {
        #pragma unroll
        for (int i = 0; i < 16; i++) {
            int idx = tid + i * 256;
            int r = idx >> 5, c = idx & 31;
            int gr = rowBase + r;
            As[r][c] = (gr < Mr) ? A[(size_t)gr * Kd + k0 + c] : 0.f;
        }
        #pragma unroll
        for (int i = 0; i < 8; i++) {
            int idx = tid + i * 256;
            int r = idx >> 6, c = idx & 63;
            Bs[r][c] = W[(size_t)(k0 + r) * Nc + colBase + c];
        }
        __syncthreads();
        #pragma unroll
        for (int kk = 0; kk < 32; kk++) {
            float a[8], b0[4];
            #pragma unroll
            for (int i = 0; i < 8; i++) a[i] = As[row0 + i][kk];
            #pragma unroll
            for (int j = 0; j < 4; j++) b0[j] = Bs[kk][col0 + j];
            #pragma unroll
            for (int i = 0; i < 8; i++)
                #pragma unroll
                for (int j = 0; j < 4; j++) acc[i][j] += a[i] * b0[j];
        }
        __syncthreads();
    }
    #pragma unroll
    for (int i = 0; i < 8; i++) {
        int r = rowBase + row0 + i;
        if (r < Mr) {
            #pragma unroll
            for (int j = 0; j < 4; j++) {
                int c = colBase + col0 + j;
                float v = acc[i][j] + bias[c];
                if (RELU) v = fmaxf(v, 0.f);
                C[(size_t)r*Nc + c] = v;
            }
        }
    }
}

// ---------------- attention: one block per (b,h) ----------------
__global__ __launch_bounds__(256) void attn_kernel(
    const float* __restrict__ Q, const float* __restrict__ Kd,
    const float* __restrict__ Vd, float* __restrict__ attnw,
    float* __restrict__ attn_out)
{
    extern __shared__ float sm[];
    float* Ss = sm;                    // T_*M_
    float* Qs = Ss + T_*M_;            // T_*HD_
    float* Vs = Qs + T_*HD_;           // 128*HD_
    __shared__ float red[256];
    int tid = threadIdx.x;
    int b = blockIdx.x / H_, h = blockIdx.x % H_;

    for (int i = tid; i < T_*HD_; i += 256) {
        int t = i >> 6, d = i & 63;
        Qs[i] = Q[(size_t)(b*T_ + t)*QD + h*HD_ + d];
    }
    __syncthreads();

    for (int m = tid; m < M_; m += 256) {
        float acc[T_];
        #pragma unroll
        for (int t = 0; t < T_; t++) acc[t] = 0.f;
        const float* kp = Kd + (size_t)(b*M_ + m)*QD + h*HD_;
        #pragma unroll 4
        for (int d = 0; d < HD_; d++) {
            float kv = kp[d];
            #pragma unroll
            for (int t = 0; t < T_; t++) acc[t] += Qs[t*HD_ + d] * kv;
        }
        #pragma unroll
        for (int t = 0; t < T_; t++) Ss[t*M_ + m] = acc[t] * 0.125f;
    }
    __syncthreads();

    for (int t = 0; t < T_; t++) {
        float mx = -1e30f;
        for (int m = tid; m < M_; m += 256) mx = fmaxf(mx, Ss[t*M_ + m]);
        red[tid] = mx; __syncthreads();
        for (int s = 128; s > 0; s >>= 1) {
            if (tid < s) red[tid] = fmaxf(red[tid], red[tid + s]);
            __syncthreads();
        }
        mx = red[0]; __syncthreads();
        float sum = 0.f;
        for (int m = tid; m < M_; m += 256) {
            float e = __expf(Ss[t*M_ + m] - mx);
            Ss[t*M_ + m] = e;
            sum += e;
        }
        red[tid] = sum; __syncthreads();
        for (int s = 128; s > 0; s >>= 1) {
            if (tid < s) red[tid] += red[tid + s];
            __syncthreads();
        }
        float inv = 1.f / red[0]; __syncthreads();
        for (int m = tid; m < M_; m += 256) {
            float p = Ss[t*M_ + m] * inv;
            Ss[t*M_ + m] = p;
            attnw[((size_t)(b*T_ + t)*H_ + h)*M_ + m] = p;
        }
        __syncthreads();
    }

    int d = tid & 63, t0 = tid >> 6;
    float acc4[4] = {0.f, 0.f, 0.f, 0.f};
    for (int m0 = 0; m0 < M_; m0 += 128) {
        for (int i = tid; i < 128*64; i += 256) {
            int r = i >> 6, c = i & 63;
            Vs[i] = Vd[(size_t)(b*M_ + m0 + r)*QD + h*HD_ + c];
        }
        __syncthreads();
        for (int m = 0; m < 128; m++) {
            float v = Vs[m*64 + d];
            #pragma unroll
            for (int j = 0; j < 4; j++) {
                int t = t0 + 4*j;
                float w2 = (t < T_) ? Ss[t*M_ + m0 + m] : 0.f;
                acc4[j] += w2 * v;
            }
        }
        __syncthreads();
    }
    #pragma unroll
    for (int j = 0; j < 4; j++) {
        int t = t0 + 4*j;
        if (t < T_) attn_out[(size_t)(b*T_ + t)*QD + h*HD_ + d] = acc4[j];
    }
}

// ---------------- residual add + LayerNorm ----------------
__global__ __launch_bounds__(256) void add_ln_kernel(
    const float* __restrict__ A, const float* __restrict__ Bv,
    const float* __restrict__ g, const float* __restrict__ be,
    float* __restrict__ out)
{
    __shared__ float xs[QD];
    __shared__ float red[256];
    int r = blockIdx.x, tid = threadIdx.x;
    float lsum = 0.f;
    for (int i = tid; i < QD; i += 256) {
        float v = A[(size_t)r*QD + i] + Bv[(size_t)r*QD + i];
        xs[i] = v;
        lsum += v;
    }
    red[tid] = lsum; __syncthreads();
    for (int s = 128; s > 0; s >>= 1) {
        if (tid < s) red[tid] += red[tid + s];
        __syncthreads();
    }
    float mu = red[0] / QD; __syncthreads();
    float lv = 0.f;
    for (int i = tid; i < QD; i += 256) {
        float d0 = xs[i] - mu;
        lv += d0 * d0;
    }
    red[tid] = lv; __syncthreads();
    for (int s = 128; s > 0; s >>= 1) {
        if (tid < s) red[tid] += red[tid + s];
        __syncthreads();
    }
    float inv = rsqrtf(red[0] / QD + EPS_); __syncthreads();
    for (int i = tid; i < QD; i += 256)
        out[(size_t)r*QD + i] = (xs[i] - mu) * inv * g[i] + be[i];
}

// ---------------- launch ----------------
extern "C" void kernel_launch(void* const* d_in, const int* in_sizes, int n_in,
                              void* d_out, int out_size)
{
    const float* X   = (const float*)d_in[0];
    const float* KV  = (const float*)d_in[1];
    const float* WQ  = (const float*)d_in[2];
    const float* bQ  = (const float*)d_in[3];
    const float* WK  = (const float*)d_in[4];
    const float* bK  = (const float*)d_in[5];
    const float* WV  = (const float*)d_in[6];
    const float* bV  = (const float*)d_in[7];
    const float* W1  = (const float*)d_in[8];
    const float* b1  = (const float*)d_in[9];
    const float* W2  = (const float*)d_in[10];
    const float* b2  = (const float*)d_in[11];
    const float* g1  = (const float*)d_in[12];
    const float* be1 = (const float*)d_in[13];
    const float* g2  = (const float*)d_in[14];
    const float* be2 = (const float*)d_in[15];

    float* out   = (float*)d_out;
    float* attnw = out + (size_t)BT*QD;

    float *Qp, *Kp, *Vp, *Ap, *X1, *Hm, *Fp;
    cudaGetSymbolAddress((void**)&Qp, g_Q);
    cudaGetSymbolAddress((void**)&Kp, g_K);
    cudaGetSymbolAddress((void**)&Vp, g_V);
    cudaGetSymbolAddress((void**)&Ap, g_attn);
    cudaGetSymbolAddress((void**)&X1, g_x1);
    cudaGetSymbolAddress((void**)&Hm, g_h);
    cudaGetSymbolAddress((void**)&Fp, g_ff);

    qproj_kernel<<<dim3(BT, QD/128), 128>>>(X, WQ, bQ, Qp);

    // K/V projection — tf32 tensor cores
    kvproj_tc_kernel<<<dim3(R_/128, QD/64), 256>>>(KV, WK, bK, WV, bV, Kp, Vp);

    const int SMEM_ATTN = (T_*M_ + T_*HD_ + 128*HD_) * (int)sizeof(float);
    cudaFuncSetAttribute(attn_kernel, cudaFuncAttributeMaxDynamicSharedMemorySize, SMEM_ATTN);
    attn_kernel<<<B_*H_, 256, SMEM_ATTN>>>(Qp, Kp, Vp, attnw, Ap);

    add_ln_kernel<<<BT, 256>>>(X, Ap, g1, be1, X1);

    gemm_bias_kernel<true ><<<dim3((BT+127)/128, FF_/64), 256>>>(X1, W1, b1, Hm, BT, FF_, QD);
    gemm_bias_kernel<false><<<dim3((BT+127)/128, QD/64), 256>>>(Hm, W2, b2, Fp, BT, QD, FF_);

    add_ln_kernel<<<BT, 256>>>(X1, Fp, g2, be2, out);
}

// round 5
// speedup vs baseline: 5.5508x; 2.4043x over previous
#include <cuda_runtime.h>
#include <cstdint>
#include <cstddef>

#define B_   32
#define T_   14
#define M_   2048
#define QD   768
#define KVD  1024
#define H_   12
#define HD_  64
#define FF_  3072
#define BT   (B_*T_)      // 448
#define TH   (T_*H_)      // 168
#define EPS_ 1e-5f

// ---------------- scratch (device globals; no allocation allowed) ----------------
__device__ float g_Q[BT*QD];                    // Q projection
__device__ float g_Qt[(size_t)B_*TH*KVD];       // Qt = Q . WK^T   (22 MB)
__device__ float g_c[B_*TH];                    // per-row logit constant (Q . bK)
__device__ float g_S[(size_t)B_*TH*M_];         // raw scores QtX  (44 MB)
__device__ float g_Ap[(size_t)H_*BT*KVD];       // A' = P . X, layout [h][bt][e] (22 MB)
__device__ float g_attn[BT*QD];
__device__ float g_x1[BT*QD];
__device__ float g_h[BT*FF_];
__device__ float g_ff[BT*QD];

// ---------------- helpers ----------------
__device__ __forceinline__ uint32_t f2tf32(float x) {
    uint32_t r;
    asm("cvt.rna.tf32.f32 %0, %1;" : "=r"(r) : "f"(x));
    return r;
}

__device__ __forceinline__ void mma_tf32(float* c, const uint32_t* a, uint32_t b0, uint32_t b1) {
    asm volatile(
        "mma.sync.aligned.m16n8k8.row.col.f32.tf32.tf32.f32 "
        "{%0,%1,%2,%3}, {%4,%5,%6,%7}, {%8,%9}, {%0,%1,%2,%3};\n"
        : "+f"(c[0]), "+f"(c[1]), "+f"(c[2]), "+f"(c[3])
        : "r"(a[0]), "r"(a[1]), "r"(a[2]), "r"(a[3]), "r"(b0), "r"(b1));
}

// ---------------- Q projection: per-expert-token weight matrices ----------------
__global__ __launch_bounds__(128) void qproj_kernel(
    const float* __restrict__ X, const float* __restrict__ WQ,
    const float* __restrict__ bQ, float* __restrict__ Q)
{
    int bt  = blockIdx.x;
    int t   = bt % T_;
    int col = blockIdx.y * 128 + threadIdx.x;
    __shared__ float xs[QD];
    for (int i = threadIdx.x; i < QD; i += 128) xs[i] = X[(size_t)bt*QD + i];
    __syncthreads();
    const float* W = WQ + (size_t)t * QD * QD;
    float acc = bQ[t*QD + col];
    #pragma unroll 8
    for (int e = 0; e < QD; e++) acc += xs[e] * W[(size_t)e*QD + col];
    Q[(size_t)bt*QD + col] = acc;
}

// ---------------- Qt[b,t,h,e] = sum_d Q[bt, h*64+d] * WK[e, h*64+d] ----------------
// grid (H_, BT/64, KVD/64), block 256, each thread 4x4 outputs, K=64 resident.
__global__ __launch_bounds__(256) void qt_kernel(
    const float* __restrict__ Q, const float* __restrict__ WK,
    float* __restrict__ Qt)
{
    int h  = blockIdx.x;
    int rt = blockIdx.y;   // bt tile (64)
    int et = blockIdx.z;   // e tile (64)
    __shared__ float Asq[64][65];
    __shared__ float Bsq[64][65];
    int tid = threadIdx.x;
    #pragma unroll
    for (int i = 0; i < 16; i += 16) {}  // no-op
    {
        int idx = tid;             // 256 threads x 16 float -> 4096 floats = 64x64
        #pragma unroll
        for (int it = 0; it < 4; it++) {
            int id = idx + it * 256;
            int r = id >> 4, c4 = (id & 15) << 2;
            float4 v = *(const float4*)&Q[(size_t)(rt*64 + r)*QD + h*HD_ + c4];
            Asq[r][c4+0] = v.x; Asq[r][c4+1] = v.y; Asq[r][c4+2] = v.z; Asq[r][c4+3] = v.w;
            float4 w = *(const float4*)&WK[(size_t)(et*64 + r)*QD + h*HD_ + c4];
            Bsq[r][c4+0] = w.x; Bsq[r][c4+1] = w.y; Bsq[r][c4+2] = w.z; Bsq[r][c4+3] = w.w;
        }
    }
    __syncthreads();
    int r0 = (tid >> 4) * 4, e0 = (tid & 15) * 4;
    float acc[4][4];
    #pragma unroll
    for (int i = 0; i < 4; i++)
        #pragma unroll
        for (int j = 0; j < 4; j++) acc[i][j] = 0.f;
    #pragma unroll 8
    for (int d = 0; d < 64; d++) {
        float a[4], b[4];
        #pragma unroll
        for (int i = 0; i < 4; i++) a[i] = Asq[r0+i][d];
        #pragma unroll
        for (int j = 0; j < 4; j++) b[j] = Bsq[e0+j][d];
        #pragma unroll
        for (int i = 0; i < 4; i++)
            #pragma unroll
            for (int j = 0; j < 4; j++) acc[i][j] += a[i]*b[j];
    }
    #pragma unroll
    for (int i = 0; i < 4; i++) {
        int bt = rt*64 + r0 + i;
        int b  = bt / T_, t = bt % T_;
        float* dst = Qt + ((size_t)(b*TH + t*H_ + h))*KVD + et*64 + e0;
        #pragma unroll
        for (int j = 0; j < 4; j++) dst[j] = acc[i][j];
    }
}

// ---------------- c[b*TH + t*H + h] = dot(Q[bt, h*64:], bK[h*64:]) ----------------
__global__ __launch_bounds__(32) void crow_kernel(
    const float* __restrict__ Q, const float* __restrict__ bK, float* __restrict__ c)
{
    int bt = blockIdx.x, h = blockIdx.y;
    int lane = threadIdx.x;
    float s = Q[(size_t)bt*QD + h*HD_ + lane]      * bK[h*HD_ + lane]
            + Q[(size_t)bt*QD + h*HD_ + 32 + lane] * bK[h*HD_ + 32 + lane];
    #pragma unroll
    for (int o = 16; o > 0; o >>= 1) s += __shfl_down_sync(0xffffffffu, s, o);
    if (lane == 0) {
        int b = bt / T_, t = bt % T_;
        c[b*TH + t*H_ + h] = s;
    }
}

// ---------------- scores: S[b] = Qt[b] (168x1024) . X[b]^T (1024x2048) ----------------
// block tile 64 rows x 128 m-cols, K chunk 32, tf32 MMA. grid (B_, 3, 16).
__global__ __launch_bounds__(256) void scores_kernel(
    const float* __restrict__ Qt, const float* __restrict__ X,
    float* __restrict__ S)
{
    __shared__ uint32_t As[64][36];
    __shared__ uint32_t Bs[128][36];
    int tid = threadIdx.x;
    int lane = tid & 31, w = tid >> 5;
    int warpM = w & 1, warpN = w >> 1;       // 2 x 4 warps
    int b = blockIdx.x;
    int rowBase = blockIdx.y * 64;
    int colBase = blockIdx.z * 128;
    int lg = lane >> 2, lt = lane & 3;

    const float* Ag = Qt + (size_t)b * TH * KVD;
    const float* Bg = X  + (size_t)b * M_ * KVD;

    float acc[2][4][4];
    #pragma unroll
    for (int mi = 0; mi < 2; mi++)
        #pragma unroll
        for (int ni = 0; ni < 4; ni++)
            #pragma unroll
            for (int q = 0; q < 4; q++) acc[mi][ni][q] = 0.f;

    for (int k0 = 0; k0 < KVD; k0 += 32) {
        // As: 64x32 from Qt (guard row < 168)
        #pragma unroll
        for (int i = 0; i < 2; i++) {
            int idx = tid + i * 256;
            int r = idx >> 3, c4 = (idx & 7) << 2;
            int gr = rowBase + r;
            float4 v = make_float4(0.f,0.f,0.f,0.f);
            if (gr < TH) v = *(const float4*)&Ag[(size_t)gr*KVD + k0 + c4];
            As[r][c4+0] = f2tf32(v.x); As[r][c4+1] = f2tf32(v.y);
            As[r][c4+2] = f2tf32(v.z); As[r][c4+3] = f2tf32(v.w);
        }
        // Bs: 128x32 from X rows (m-major, k contiguous)
        #pragma unroll
        for (int i = 0; i < 4; i++) {
            int idx = tid + i * 256;
            int r = idx >> 3, c4 = (idx & 7) << 2;
            float4 v = *(const float4*)&Bg[(size_t)(colBase + r)*KVD + k0 + c4];
            Bs[r][c4+0] = f2tf32(v.x); Bs[r][c4+1] = f2tf32(v.y);
            Bs[r][c4+2] = f2tf32(v.z); Bs[r][c4+3] = f2tf32(v.w);
        }
        __syncthreads();
        #pragma unroll
        for (int ks = 0; ks < 4; ks++) {
            int kb = ks * 8;
            uint32_t a[2][4];
            #pragma unroll
            for (int mi = 0; mi < 2; mi++) {
                int r = warpM * 32 + mi * 16 + lg;
                a[mi][0] = As[r][kb + lt];
                a[mi][1] = As[r + 8][kb + lt];
                a[mi][2] = As[r][kb + lt + 4];
                a[mi][3] = As[r + 8][kb + lt + 4];
            }
            #pragma unroll
            for (int ni = 0; ni < 4; ni++) {
                int n = warpN * 32 + ni * 8 + lg;
                uint32_t b0 = Bs[n][kb + lt];
                uint32_t b1 = Bs[n][kb + lt + 4];
                #pragma unroll
                for (int mi = 0; mi < 2; mi++) mma_tf32(acc[mi][ni], a[mi], b0, b1);
            }
        }
        __syncthreads();
    }
    // store raw scores
    float* Sg = S + (size_t)b * TH * M_;
    #pragma unroll
    for (int mi = 0; mi < 2; mi++) {
        #pragma unroll
        for (int ni = 0; ni < 4; ni++) {
            int r = rowBase + warpM * 32 + mi * 16 + lg;
            int cc = colBase + warpN * 32 + ni * 8 + lt * 2;
            if (r < TH) {
                float2 v; v.x = acc[mi][ni][0]; v.y = acc[mi][ni][1];
                *(float2*)&Sg[(size_t)r*M_ + cc] = v;
            }
            if (r + 8 < TH) {
                float2 v; v.x = acc[mi][ni][2]; v.y = acc[mi][ni][3];
                *(float2*)&Sg[(size_t)(r+8)*M_ + cc] = v;
            }
        }
    }
}

// ---------------- softmax over m: attn_w = softmax((S + c)/8) ----------------
// grid (B_*TH), block 256.
__global__ __launch_bounds__(256) void softmax_kernel(
    const float* __restrict__ S, const float* __restrict__ c,
    float* __restrict__ P)
{
    __shared__ float red[256];
    int row = blockIdx.x, tid = threadIdx.x;
    const float* s = S + (size_t)row * M_;
    float*       p = P + (size_t)row * M_;
    float cv = c[row];
    float vals[8];
    float mx = -1e30f;
    #pragma unroll
    for (int i = 0; i < 8; i++) {
        float v = (s[tid + i*256] + cv) * 0.125f;
        vals[i] = v;
        mx = fmaxf(mx, v);
    }
    red[tid] = mx; __syncthreads();
    for (int o = 128; o > 0; o >>= 1) {
        if (tid < o) red[tid] = fmaxf(red[tid], red[tid + o]);
        __syncthreads();
    }
    mx = red[0]; __syncthreads();
    float sum = 0.f;
    #pragma unroll
    for (int i = 0; i < 8; i++) {
        vals[i] = __expf(vals[i] - mx);
        sum += vals[i];
    }
    red[tid] = sum; __syncthreads();
    for (int o = 128; o > 0; o >>= 1) {
        if (tid < o) red[tid] += red[tid + o];
        __syncthreads();
    }
    float inv = 1.f / red[0];
    #pragma unroll
    for (int i = 0; i < 8; i++) p[tid + i*256] = vals[i] * inv;
}

// ---------------- A' = P[b] (168x2048) . X[b] (2048x1024), out layout [h][bt][e] ----------------
// block tile 64 rows x 128 e-cols, K chunk 32, tf32 MMA. grid (B_, 3, 8).
__global__ __launch_bounds__(256) void aprime_kernel(
    const float* __restrict__ P, const float* __restrict__ X,
    float* __restrict__ Ap)
{
    __shared__ uint32_t As[64][36];
    __shared__ uint32_t Bs[32][136];
    int tid = threadIdx.x;
    int lane = tid & 31, w = tid >> 5;
    int warpM = w & 1, warpN = w >> 1;
    int b = blockIdx.x;
    int rowBase = blockIdx.y * 64;
    int colBase = blockIdx.z * 128;
    int lg = lane >> 2, lt = lane & 3;

    const float* Ag = P + (size_t)b * TH * M_;
    const float* Bg = X + (size_t)b * M_ * KVD;

    float acc[2][4][4];
    #pragma unroll
    for (int mi = 0; mi < 2; mi++)
        #pragma unroll
        for (int ni = 0; ni < 4; ni++)
            #pragma unroll
            for (int q = 0; q < 4; q++) acc[mi][ni][q] = 0.f;

    for (int k0 = 0; k0 < M_; k0 += 32) {
        #pragma unroll
        for (int i = 0; i < 2; i++) {
            int idx = tid + i * 256;
            int r = idx >> 3, c4 = (idx & 7) << 2;
            int gr = rowBase + r;
            float4 v = make_float4(0.f,0.f,0.f,0.f);
            if (gr < TH) v = *(const float4*)&Ag[(size_t)gr*M_ + k0 + c4];
            As[r][c4+0] = f2tf32(v.x); As[r][c4+1] = f2tf32(v.y);
            As[r][c4+2] = f2tf32(v.z); As[r][c4+3] = f2tf32(v.w);
        }
        // Bs[k][n]: X rows k0..k0+31, cols colBase..+127 (n contiguous)
        #pragma unroll
        for (int i = 0; i < 4; i++) {
            int idx = tid + i * 256;
            int r = idx >> 5, c4 = (idx & 31) << 2;
            float4 v = *(const float4*)&Bg[(size_t)(k0 + r)*KVD + colBase + c4];
            Bs[r][c4+0] = f2tf32(v.x); Bs[r][c4+1] = f2tf32(v.y);
            Bs[r][c4+2] = f2tf32(v.z); Bs[r][c4+3] = f2tf32(v.w);
        }
        __syncthreads();
        #pragma unroll
        for (int ks = 0; ks < 4; ks++) {
            int kb = ks * 8;
            uint32_t a[2][4];
            #pragma unroll
            for (int mi = 0; mi < 2; mi++) {
                int r = warpM * 32 + mi * 16 + lg;
                a[mi][0] = As[r][kb + lt];
                a[mi][1] = As[r + 8][kb + lt];
                a[mi][2] = As[r][kb + lt + 4];
                a[mi][3] = As[r + 8][kb + lt + 4];
            }
            #pragma unroll
            for (int ni = 0; ni < 4; ni++) {
                int n = warpN * 32 + ni * 8 + lg;
                uint32_t b0 = Bs[kb + lt][n];
                uint32_t b1 = Bs[kb + lt + 4][n];
                #pragma unroll
                for (int mi = 0; mi < 2; mi++) mma_tf32(acc[mi][ni], a[mi], b0, b1);
            }
        }
        __syncthreads();
    }
    // store: row r (= t*12+h) of batch b -> Ap[h][b*14+t][e]
    #pragma unroll
    for (int mi = 0; mi < 2; mi++) {
        #pragma unroll
        for (int ni = 0; ni < 4; ni++) {
            int cc = colBase + warpN * 32 + ni * 8 + lt * 2;
            #pragma unroll
            for (int half = 0; half < 2; half++) {
                int r = rowBase + warpM * 32 + mi * 16 + lg + half * 8;
                if (r < TH) {
                    int t = r / H_, h = r % H_;
                    int bt = b * T_ + t;
                    float2 v;
                    v.x = acc[mi][ni][half*2 + 0];
                    v.y = acc[mi][ni][half*2 + 1];
                    *(float2*)&Ap[((size_t)h*BT + bt)*KVD + cc] = v;
                }
            }
        }
    }
}

// ---------------- attn_out[bt, h*64+d] = sum_e Ap[h][bt][e] WV[e, h*64+d] + bV ----------------
// grid (H_, 7), block 256, tile 64x64, K chunk 32, SIMT fp32 (0.7 GFLOP total).
__global__ __launch_bounds__(256) void attnout_kernel(
    const float* __restrict__ Ap, const float* __restrict__ WV,
    const float* __restrict__ bV, float* __restrict__ O)
{
    __shared__ float As[64][33];
    __shared__ float Bs[32][65];
    int h = blockIdx.x;
    int rowBase = blockIdx.y * 64;
    int tid = threadIdx.x;
    int r0 = (tid >> 4) * 4, c0 = (tid & 15) * 4;
    float acc[4][4];
    #pragma unroll
    for (int i = 0; i < 4; i++)
        #pragma unroll
        for (int j = 0; j < 4; j++) acc[i][j] = 0.f;

    const float* Ag = Ap + (size_t)h * BT * KVD;
    for (int k0 = 0; k0 < KVD; k0 += 32) {
        #pragma unroll
        for (int i = 0; i < 2; i++) {
            int idx = tid + i * 256;
            int r = idx >> 3, c4 = (idx & 7) << 2;
            float4 v = *(const float4*)&Ag[(size_t)(rowBase + r)*KVD + k0 + c4];
            As[r][c4+0] = v.x; As[r][c4+1] = v.y; As[r][c4+2] = v.z; As[r][c4+3] = v.w;
        }
        #pragma unroll
        for (int i = 0; i < 2; i++) {
            int idx = tid + i * 256;
            int r = idx >> 4, c4 = (idx & 15) << 2;
            float4 v = *(const float4*)&WV[(size_t)(k0 + r)*QD + h*HD_ + c4];
            Bs[r][c4+0] = v.x; Bs[r][c4+1] = v.y; Bs[r][c4+2] = v.z; Bs[r][c4+3] = v.w;
        }
        __syncthreads();
        #pragma unroll
        for (int kk = 0; kk < 32; kk++) {
            float a[4], bb[4];
            #pragma unroll
            for (int i = 0; i < 4; i++) a[i] = As[r0+i][kk];
            #pragma unroll
            for (int j = 0; j < 4; j++) bb[j] = Bs[kk][c0+j];
            #pragma unroll
            for (int i = 0; i < 4; i++)
                #pragma unroll
                for (int j = 0; j < 4; j++) acc[i][j] += a[i]*bb[j];
        }
        __syncthreads();
    }
    #pragma unroll
    for (int i = 0; i < 4; i++) {
        int bt = rowBase + r0 + i;
        #pragma unroll
        for (int j = 0; j < 4; j++)
            O[(size_t)bt*QD + h*HD_ + c0 + j] = acc[i][j] + bV[h*HD_ + c0 + j];
    }
}

// ---------------- generic GEMM with bias (+optional ReLU), M-guarded ----------------
template<bool RELU>
__global__ __launch_bounds__(256) void gemm_bias_kernel(
    const float* __restrict__ A, const float* __restrict__ W,
    const float* __restrict__ bias, float* __restrict__ C,
    int Mr, int Nc, int Kd)
{
    __shared__ float As[128][33];
    __shared__ float Bs[32][64];
    int tid = threadIdx.x;
    int rowBase = blockIdx.x * 128;
    int colBase = blockIdx.y * 64;
    int tx = tid & 15, ty = tid >> 4;
    int row0 = ty * 8, col0 = tx * 4;
    float acc[8][4];
    #pragma unroll
    for (int i = 0; i < 8; i++)
        #pragma unroll
        for (int j = 0; j < 4; j++) acc[i][j] = 0.f;

    for (int k0 = 0; k0 < Kd; k0 += 32) {
        #pragma unroll
        for (int i = 0; i < 16; i++) {
            int idx = tid + i * 256;
            int r = idx >> 5, c = idx & 31;
            int gr = rowBase + r;
            As[r][c] = (gr < Mr) ? A[(size_t)gr * Kd + k0 + c] : 0.f;
        }
        #pragma unroll
        for (int i = 0; i < 8; i++) {
            int idx = tid + i * 256;
            int r = idx >> 6, c = idx & 63;
            Bs[r][c] = W[(size_t)(k0 + r) * Nc + colBase + c];
        }
        __syncthreads();
        #pragma unroll
        for (int kk = 0; kk < 32; kk++) {
            float a[8], b0[4];
            #pragma unroll
            for (int i = 0; i < 8; i++) a[i] = As[row0 + i][kk];
            #pragma unroll
            for (int j = 0; j < 4; j++) b0[j] = Bs[kk][col0 + j];
            #pragma unroll
            for (int i = 0; i < 8; i++)
                #pragma unroll
                for (int j = 0; j < 4; j++) acc[i][j] += a[i] * b0[j];
        }
        __syncthreads();
    }
    #pragma unroll
    for (int i = 0; i < 8; i++) {
        int r = rowBase + row0 + i;
        if (r < Mr) {
            #pragma unroll
            for (int j = 0; j < 4; j++) {
                int c = colBase + col0 + j;
                float v = acc[i][j] + bias[c];
                if (RELU) v = fmaxf(v, 0.f);
                C[(size_t)r*Nc + c] = v;
            }
        }
    }
}

// ---------------- residual add + LayerNorm ----------------
__global__ __launch_bounds__(256) void add_ln_kernel(
    const float* __restrict__ A, const float* __restrict__ Bv,
    const float* __restrict__ g, const float* __restrict__ be,
    float* __restrict__ out)
{
    __shared__ float xs[QD];
    __shared__ float red[256];
    int r = blockIdx.x, tid = threadIdx.x;
    float lsum = 0.f;
    for (int i = tid; i < QD; i += 256) {
        float v = A[(size_t)r*QD + i] + Bv[(size_t)r*QD + i];
        xs[i] = v;
        lsum += v;
    }
    red[tid] = lsum; __syncthreads();
    for (int s = 128; s > 0; s >>= 1) {
        if (tid < s) red[tid] += red[tid + s];
        __syncthreads();
    }
    float mu = red[0] / QD; __syncthreads();
    float lv = 0.f;
    for (int i = tid; i < QD; i += 256) {
        float d0 = xs[i] - mu;
        lv += d0 * d0;
    }
    red[tid] = lv; __syncthreads();
    for (int s = 128; s > 0; s >>= 1) {
        if (tid < s) red[tid] += red[tid + s];
        __syncthreads();
    }
    float inv = rsqrtf(red[0] / QD + EPS_); __syncthreads();
    for (int i = tid; i < QD; i += 256)
        out[(size_t)r*QD + i] = (xs[i] - mu) * inv * g[i] + be[i];
}

// ---------------- launch ----------------
extern "C" void kernel_launch(void* const* d_in, const int* in_sizes, int n_in,
                              void* d_out, int out_size)
{
    const float* X   = (const float*)d_in[0];   // expert_tokens [B,T,QD]
    const float* KV  = (const float*)d_in[1];   // key_value_embeddings [B,M,KVD]
    const float* WQ  = (const float*)d_in[2];
    const float* bQ  = (const float*)d_in[3];
    const float* WK  = (const float*)d_in[4];
    const float* bK  = (const float*)d_in[5];
    const float* WV  = (const float*)d_in[6];
    const float* bV  = (const float*)d_in[7];
    const float* W1  = (const float*)d_in[8];
    const float* b1  = (const float*)d_in[9];
    const float* W2  = (const float*)d_in[10];
    const float* b2  = (const float*)d_in[11];
    const float* g1  = (const float*)d_in[12];
    const float* be1 = (const float*)d_in[13];
    const float* g2  = (const float*)d_in[14];
    const float* be2 = (const float*)d_in[15];

    float* out   = (float*)d_out;
    float* attnw = out + (size_t)BT*QD;         // [B,T,H,M] == [B][168][2048]

    float *Qp, *Qtp, *cp, *Sp, *App, *Aop, *X1, *Hm, *Fp;
    cudaGetSymbolAddress((void**)&Qp,  g_Q);
    cudaGetSymbolAddress((void**)&Qtp, g_Qt);
    cudaGetSymbolAddress((void**)&cp,  g_c);
    cudaGetSymbolAddress((void**)&Sp,  g_S);
    cudaGetSymbolAddress((void**)&App, g_Ap);
    cudaGetSymbolAddress((void**)&Aop, g_attn);
    cudaGetSymbolAddress((void**)&X1,  g_x1);
    cudaGetSymbolAddress((void**)&Hm,  g_h);
    cudaGetSymbolAddress((void**)&Fp,  g_ff);

    // Q projection
    qproj_kernel<<<dim3(BT, QD/128), 128>>>(X, WQ, bQ, Qp);

    // Qt = Q . WK^T (per head), c = Q . bK
    qt_kernel<<<dim3(H_, BT/64, KVD/64), 256>>>(Qp, WK, Qtp);
    crow_kernel<<<dim3(BT, H_), 32>>>(Qp, bK, cp);

    // scores = Qt . X^T  (22.5 GFLOP, tf32 MMA)
    scores_kernel<<<dim3(B_, 3, M_/128), 256>>>(Qtp, KV, Sp);

    // attn_w = softmax((scores + c)/8)  -> written directly to output
    softmax_kernel<<<B_*TH, 256>>>(Sp, cp, attnw);

    // A' = P . X  (22.5 GFLOP, tf32 MMA)
    aprime_kernel<<<dim3(B_, 3, KVD/128), 256>>>(attnw, KV, App);

    // attn_out = A' . WV + bV
    attnout_kernel<<<dim3(H_, BT/64), 256>>>(App, WV, bV, Aop);

    // x1 = LN(tokens + attn_out)
    add_ln_kernel<<<BT, 256>>>(X, Aop, g1, be1, X1);

    // FFN
    gemm_bias_kernel<true ><<<dim3((BT+127)/128, FF_/64), 256>>>(X1, W1, b1, Hm, BT, FF_, QD);
    gemm_bias_kernel<false><<<dim3((BT+127)/128, QD/64), 256>>>(Hm, W2, b2, Fp, BT, QD, FF_);

    // out = LN(x1 + ff)
    add_ln_kernel<<<BT, 256>>>(X1, Fp, g2, be2, out);
}

// round 10
// speedup vs baseline: 9.1021x; 1.6398x over previous
#include <cuda_runtime.h>
#include <cstdint>
#include <cstddef>

#define B_   32
#define T_   14
#define M_   2048
#define QD   768
#define KVD  1024
#define H_   12
#define HD_  64
#define FF_  3072
#define BT   (B_*T_)      // 448
#define TH   (T_*H_)      // 168
#define EPS_ 1e-5f

// ---------------- scratch (device globals; no allocation allowed) ----------------
__device__ float g_Q[BT*QD];
__device__ float g_Qt[(size_t)B_*TH*KVD];       // 22 MB
__device__ float g_c[B_*TH];
__device__ float g_S[(size_t)B_*TH*M_];         // 44 MB
__device__ float g_Ap[(size_t)H_*BT*KVD];       // 22 MB
__device__ float g_attn[BT*QD];
__device__ float g_x1[BT*QD];
__device__ float g_h[BT*FF_];
__device__ float g_ff[BT*QD];

// ---------------- helpers ----------------
__device__ __forceinline__ void mma_tf32(float* c, const uint32_t* a, uint32_t b0, uint32_t b1) {
    asm volatile(
        "mma.sync.aligned.m16n8k8.row.col.f32.tf32.tf32.f32 "
        "{%0,%1,%2,%3}, {%4,%5,%6,%7}, {%8,%9}, {%0,%1,%2,%3};\n"
        : "+f"(c[0]), "+f"(c[1]), "+f"(c[2]), "+f"(c[3])
        : "r"(a[0]), "r"(a[1]), "r"(a[2]), "r"(a[3]), "r"(b0), "r"(b1));
}

__device__ __forceinline__ void cpa16(uint32_t saddr, const void* g, uint32_t sz) {
    asm volatile("cp.async.cg.shared.global [%0], [%1], 16, %2;"
                 :: "r"(saddr), "l"(g), "r"(sz));
}
__device__ __forceinline__ void cpa_commit() { asm volatile("cp.async.commit_group;"); }
__device__ __forceinline__ void cpa_wait1()  { asm volatile("cp.async.wait_group 1;"); }
__device__ __forceinline__ void cpa_wait0()  { asm volatile("cp.async.wait_group 0;"); }

// smem layouts (uint32 words)
#define SC_A_STRIDE 36
#define SC_B_STRIDE 36
#define SC_A_WORDS  (64*SC_A_STRIDE)     // per buffer
#define SC_B_WORDS  (256*SC_B_STRIDE)
#define SC_SMEM_BYTES ((2*SC_A_WORDS + 2*SC_B_WORDS)*4)    // 92160

#define AP_B_STRIDE 264
#define AP_A_WORDS  (64*SC_A_STRIDE)
#define AP_B_WORDS  (32*AP_B_STRIDE)
#define AP_SMEM_BYTES ((2*AP_A_WORDS + 2*AP_B_WORDS)*4)    // 86016

// ---------------- Q projection: one GEMM per expert-token t ----------------
// Xt [32, 768] (rows = batch) x WQ_t [768, 768] -> Q rows (b*T_+t)
__global__ __launch_bounds__(256) void qproj_kernel(
    const float* __restrict__ X, const float* __restrict__ WQ,
    const float* __restrict__ bQ, float* __restrict__ Q)
{
    int t = blockIdx.x;
    int colBase = blockIdx.y * 128;
    __shared__ float As[32][33];
    __shared__ float Bs[32][132];
    int tid = threadIdx.x;
    int r0 = (tid >> 5) * 4;       // 8 groups x 4 rows = 32
    int c0 = (tid & 31) * 4;       // 32 groups x 4 cols = 128
    float acc[4][4];
    #pragma unroll
    for (int i = 0; i < 4; i++)
        #pragma unroll
        for (int j = 0; j < 4; j++) acc[i][j] = 0.f;

    const float* Wt = WQ + (size_t)t * QD * QD;
    for (int k0 = 0; k0 < QD; k0 += 32) {
        {
            int r = tid >> 3, c4 = (tid & 7) << 2;
            float4 v = *(const float4*)&X[(size_t)(r*T_ + t)*QD + k0 + c4];
            As[r][c4+0] = v.x; As[r][c4+1] = v.y; As[r][c4+2] = v.z; As[r][c4+3] = v.w;
        }
        #pragma unroll
        for (int i = 0; i < 4; i++) {
            int idx = tid + i * 256;
            int r = idx >> 5, c4 = (idx & 31) << 2;
            float4 v = *(const float4*)&Wt[(size_t)(k0 + r)*QD + colBase + c4];
            Bs[r][c4+0] = v.x; Bs[r][c4+1] = v.y; Bs[r][c4+2] = v.z; Bs[r][c4+3] = v.w;
        }
        __syncthreads();
        #pragma unroll
        for (int kk = 0; kk < 32; kk++) {
            float a[4];
            #pragma unroll
            for (int i = 0; i < 4; i++) a[i] = As[r0+i][kk];
            float4 b4 = *(float4*)&Bs[kk][c0];
            float bb[4] = {b4.x, b4.y, b4.z, b4.w};
            #pragma unroll
            for (int i = 0; i < 4; i++)
                #pragma unroll
                for (int j = 0; j < 4; j++) acc[i][j] += a[i]*bb[j];
        }
        __syncthreads();
    }
    #pragma unroll
    for (int i = 0; i < 4; i++) {
        int bt = (r0 + i)*T_ + t;
        #pragma unroll
        for (int j = 0; j < 4; j++) {
            int c = colBase + c0 + j;
            Q[(size_t)bt*QD + c] = acc[i][j] + bQ[t*QD + c];
        }
    }
}

// ---------------- Qt[b,t,h,e] = sum_d Q[bt, h*64+d] * WK[e, h*64+d] ----------------
__global__ __launch_bounds__(256) void qt_kernel(
    const float* __restrict__ Q, const float* __restrict__ WK,
    float* __restrict__ Qt)
{
    int h  = blockIdx.x;
    int rt = blockIdx.y;
    int et = blockIdx.z;
    __shared__ float Asq[64][65];
    __shared__ float Bsq[64][65];
    int tid = threadIdx.x;
    #pragma unroll
    for (int it = 0; it < 4; it++) {
        int id = tid + it * 256;
        int r = id >> 4, c4 = (id & 15) << 2;
        float4 v = *(const float4*)&Q[(size_t)(rt*64 + r)*QD + h*HD_ + c4];
        Asq[r][c4+0] = v.x; Asq[r][c4+1] = v.y; Asq[r][c4+2] = v.z; Asq[r][c4+3] = v.w;
        float4 w = *(const float4*)&WK[(size_t)(et*64 + r)*QD + h*HD_ + c4];
        Bsq[r][c4+0] = w.x; Bsq[r][c4+1] = w.y; Bsq[r][c4+2] = w.z; Bsq[r][c4+3] = w.w;
    }
    __syncthreads();
    int r0 = (tid >> 4) * 4, e0 = (tid & 15) * 4;
    float acc[4][4];
    #pragma unroll
    for (int i = 0; i < 4; i++)
        #pragma unroll
        for (int j = 0; j < 4; j++) acc[i][j] = 0.f;
    #pragma unroll 8
    for (int d = 0; d < 64; d++) {
        float a[4], b[4];
        #pragma unroll
        for (int i = 0; i < 4; i++) a[i] = Asq[r0+i][d];
        #pragma unroll
        for (int j = 0; j < 4; j++) b[j] = Bsq[e0+j][d];
        #pragma unroll
        for (int i = 0; i < 4; i++)
            #pragma unroll
            for (int j = 0; j < 4; j++) acc[i][j] += a[i]*b[j];
    }
    #pragma unroll
    for (int i = 0; i < 4; i++) {
        int bt = rt*64 + r0 + i;
        int b  = bt / T_, t = bt % T_;
        float* dst = Qt + ((size_t)(b*TH + t*H_ + h))*KVD + et*64 + e0;
        #pragma unroll
        for (int j = 0; j < 4; j++) dst[j] = acc[i][j];
    }
}

// ---------------- c row constant ----------------
__global__ __launch_bounds__(32) void crow_kernel(
    const float* __restrict__ Q, const float* __restrict__ bK, float* __restrict__ c)
{
    int bt = blockIdx.x, h = blockIdx.y;
    int lane = threadIdx.x;
    float s = Q[(size_t)bt*QD + h*HD_ + lane]      * bK[h*HD_ + lane]
            + Q[(size_t)bt*QD + h*HD_ + 32 + lane] * bK[h*HD_ + 32 + lane];
    #pragma unroll
    for (int o = 16; o > 0; o >>= 1) s += __shfl_down_sync(0xffffffffu, s, o);
    if (lane == 0) {
        int b = bt / T_, t = bt % T_;
        c[b*TH + t*H_ + h] = s;
    }
}

// ---------------- scores: S[b] = Qt[b] (168x1024) . X[b]^T -> [168, 2048] ----------------
// block 64x256, warp tile 32x64, cp.async double buffered. grid (8, 3, B_)
__global__ __launch_bounds__(256, 2) void scores_kernel(
    const float* __restrict__ Qt, const float* __restrict__ X,
    float* __restrict__ S)
{
    extern __shared__ uint32_t sm[];
    uint32_t* As = sm;                       // [2][64][36]
    uint32_t* Bs = sm + 2*SC_A_WORDS;        // [2][256][36]
    uint32_t sA = (uint32_t)__cvta_generic_to_shared(As);
    uint32_t sB = (uint32_t)__cvta_generic_to_shared(Bs);

    int tid = threadIdx.x;
    int lane = tid & 31, w = tid >> 5;
    int warpM = w & 1, warpN = w >> 1;
    int lg = lane >> 2, lt = lane & 3;
    int colBase = blockIdx.x * 256;
    int rowBase = blockIdx.y * 64;
    int b = blockIdx.z;

    const float* Ag = Qt + (size_t)b * TH * KVD;
    const float* Bg = X  + (size_t)b * M_ * KVD;

    float acc[2][8][4];
    #pragma unroll
    for (int mi = 0; mi < 2; mi++)
        #pragma unroll
        for (int ni = 0; ni < 8; ni++)
            #pragma unroll
            for (int q = 0; q < 4; q++) acc[mi][ni][q] = 0.f;

    auto loadA = [&](int kc, int buf) {
        int k0 = kc * 32;
        #pragma unroll
        for (int i = 0; i < 2; i++) {
            int idx = tid + i * 256;
            int r = idx >> 3, c4 = (idx & 7) << 2;
            int gr = rowBase + r;
            int grc = gr < TH ? gr : TH - 1;
            uint32_t sz = gr < TH ? 16u : 0u;
            cpa16(sA + ((buf*SC_A_WORDS + r*SC_A_STRIDE + c4) << 2),
                  Ag + (size_t)grc*KVD + k0 + c4, sz);
        }
    };
    auto loadB = [&](int kc, int buf) {
        int k0 = kc * 32;
        #pragma unroll
        for (int i = 0; i < 8; i++) {
            int idx = tid + i * 256;
            int r = idx >> 3, c4 = (idx & 7) << 2;
            cpa16(sB + ((buf*SC_B_WORDS + r*SC_B_STRIDE + c4) << 2),
                  Bg + (size_t)(colBase + r)*KVD + k0 + c4, 16u);
        }
    };

    const int NC = KVD / 32;
    loadA(0, 0); loadB(0, 0); cpa_commit();
    for (int kc = 0; kc < NC; kc++) {
        int cur = kc & 1;
        if (kc + 1 < NC) {
            loadA(kc+1, cur^1); loadB(kc+1, cur^1); cpa_commit();
            cpa_wait1();
        } else {
            cpa_wait0();
        }
        __syncthreads();
        const uint32_t* Ab = As + cur*SC_A_WORDS;
        const uint32_t* Bb = Bs + cur*SC_B_WORDS;
        #pragma unroll
        for (int ks = 0; ks < 4; ks++) {
            int kb = ks * 8;
            uint32_t a[2][4];
            #pragma unroll
            for (int mi = 0; mi < 2; mi++) {
                int r = warpM*32 + mi*16 + lg;
                a[mi][0] = Ab[r*SC_A_STRIDE + kb + lt];
                a[mi][1] = Ab[(r+8)*SC_A_STRIDE + kb + lt];
                a[mi][2] = Ab[r*SC_A_STRIDE + kb + lt + 4];
                a[mi][3] = Ab[(r+8)*SC_A_STRIDE + kb + lt + 4];
            }
            #pragma unroll
            for (int ni = 0; ni < 8; ni++) {
                int n = warpN*64 + ni*8 + lg;
                uint32_t b0 = Bb[n*SC_B_STRIDE + kb + lt];
                uint32_t b1 = Bb[n*SC_B_STRIDE + kb + lt + 4];
                mma_tf32(acc[0][ni], a[0], b0, b1);
                mma_tf32(acc[1][ni], a[1], b0, b1);
            }
        }
        __syncthreads();
    }

    float* Sg = S + (size_t)b * TH * M_;
    #pragma unroll
    for (int mi = 0; mi < 2; mi++) {
        #pragma unroll
        for (int ni = 0; ni < 8; ni++) {
            int r = rowBase + warpM*32 + mi*16 + lg;
            int cc = colBase + warpN*64 + ni*8 + lt*2;
            if (r < TH) {
                float2 v; v.x = acc[mi][ni][0]; v.y = acc[mi][ni][1];
                *(float2*)&Sg[(size_t)r*M_ + cc] = v;
            }
            if (r + 8 < TH) {
                float2 v; v.x = acc[mi][ni][2]; v.y = acc[mi][ni][3];
                *(float2*)&Sg[(size_t)(r+8)*M_ + cc] = v;
            }
        }
    }
}

// ---------------- softmax ----------------
__global__ __launch_bounds__(256) void softmax_kernel(
    const float* __restrict__ S, const float* __restrict__ c,
    float* __restrict__ P)
{
    __shared__ float red[256];
    int row = blockIdx.x, tid = threadIdx.x;
    const float* s = S + (size_t)row * M_;
    float*       p = P + (size_t)row * M_;
    float cv = c[row];
    float vals[8];
    float mx = -1e30f;
    #pragma unroll
    for (int i = 0; i < 8; i++) {
        float v = (s[tid + i*256] + cv) * 0.125f;
        vals[i] = v;
        mx = fmaxf(mx, v);
    }
    red[tid] = mx; __syncthreads();
    for (int o = 128; o > 0; o >>= 1) {
        if (tid < o) red[tid] = fmaxf(red[tid], red[tid + o]);
        __syncthreads();
    }
    mx = red[0]; __syncthreads();
    float sum = 0.f;
    #pragma unroll
    for (int i = 0; i < 8; i++) {
        vals[i] = __expf(vals[i] - mx);
        sum += vals[i];
    }
    red[tid] = sum; __syncthreads();
    for (int o = 128; o > 0; o >>= 1) {
        if (tid < o) red[tid] += red[tid + o];
        __syncthreads();
    }
    float inv = 1.f / red[0];
    #pragma unroll
    for (int i = 0; i < 8; i++) p[tid + i*256] = vals[i] * inv;
}

// ---------------- A' = P[b] (168x2048) . X[b] (2048x1024) -> [h][bt][e] ----------------
// block 64x256, warp tile 32x64, cp.async double buffered. grid (4, 3, B_)
__global__ __launch_bounds__(256, 2) void aprime_kernel(
    const float* __restrict__ P, const float* __restrict__ X,
    float* __restrict__ Ap)
{
    extern __shared__ uint32_t sm[];
    uint32_t* As = sm;                       // [2][64][36]
    uint32_t* Bs = sm + 2*AP_A_WORDS;        // [2][32][264]
    uint32_t sA = (uint32_t)__cvta_generic_to_shared(As);
    uint32_t sB = (uint32_t)__cvta_generic_to_shared(Bs);

    int tid = threadIdx.x;
    int lane = tid & 31, w = tid >> 5;
    int warpM = w & 1, warpN = w >> 1;
    int lg = lane >> 2, lt = lane & 3;
    int colBase = blockIdx.x * 256;
    int rowBase = blockIdx.y * 64;
    int b = blockIdx.z;

    const float* Ag = P + (size_t)b * TH * M_;
    const float* Bg = X + (size_t)b * M_ * KVD;

    float acc[2][8][4];
    #pragma unroll
    for (int mi = 0; mi < 2; mi++)
        #pragma unroll
        for (int ni = 0; ni < 8; ni++)
            #pragma unroll
            for (int q = 0; q < 4; q++) acc[mi][ni][q] = 0.f;

    auto loadA = [&](int kc, int buf) {
        int k0 = kc * 32;
        #pragma unroll
        for (int i = 0; i < 2; i++) {
            int idx = tid + i * 256;
            int r = idx >> 3, c4 = (idx & 7) << 2;
            int gr = rowBase + r;
            int grc = gr < TH ? gr : TH - 1;
            uint32_t sz = gr < TH ? 16u : 0u;
            cpa16(sA + ((buf*AP_A_WORDS + r*SC_A_STRIDE + c4) << 2),
                  Ag + (size_t)grc*M_ + k0 + c4, sz);
        }
    };
    auto loadB = [&](int kc, int buf) {
        int k0 = kc * 32;
        #pragma unroll
        for (int i = 0; i < 8; i++) {
            int idx = tid + i * 256;
            int r = idx >> 6, c4 = (idx & 63) << 2;
            cpa16(sB + ((buf*AP_B_WORDS + r*AP_B_STRIDE + c4) << 2),
                  Bg + (size_t)(k0 + r)*KVD + colBase + c4, 16u);
        }
    };

    const int NC = M_ / 32;
    loadA(0, 0); loadB(0, 0); cpa_commit();
    for (int kc = 0; kc < NC; kc++) {
        int cur = kc & 1;
        if (kc + 1 < NC) {
            loadA(kc+1, cur^1); loadB(kc+1, cur^1); cpa_commit();
            cpa_wait1();
        } else {
            cpa_wait0();
        }
        __syncthreads();
        const uint32_t* Ab = As + cur*AP_A_WORDS;
        const uint32_t* Bb = Bs + cur*AP_B_WORDS;
        #pragma unroll
        for (int ks = 0; ks < 4; ks++) {
            int kb = ks * 8;
            uint32_t a[2][4];
            #pragma unroll
            for (int mi = 0; mi < 2; mi++) {
                int r = warpM*32 + mi*16 + lg;
                a[mi][0] = Ab[r*SC_A_STRIDE + kb + lt];
                a[mi][1] = Ab[(r+8)*SC_A_STRIDE + kb + lt];
                a[mi][2] = Ab[r*SC_A_STRIDE + kb + lt + 4];
                a[mi][3] = Ab[(r+8)*SC_A_STRIDE + kb + lt + 4];
            }
            #pragma unroll
            for (int ni = 0; ni < 8; ni++) {
                int n = warpN*64 + ni*8 + lg;
                uint32_t b0 = Bb[(kb + lt)*AP_B_STRIDE + n];
                uint32_t b1 = Bb[(kb + lt + 4)*AP_B_STRIDE + n];
                mma_tf32(acc[0][ni], a[0], b0, b1);
                mma_tf32(acc[1][ni], a[1], b0, b1);
            }
        }
        __syncthreads();
    }

    #pragma unroll
    for (int mi = 0; mi < 2; mi++) {
        #pragma unroll
        for (int ni = 0; ni < 8; ni++) {
            int cc = colBase + warpN*64 + ni*8 + lt*2;
            #pragma unroll
            for (int half = 0; half < 2; half++) {
                int r = rowBase + warpM*32 + mi*16 + lg + half*8;
                if (r < TH) {
                    int t = r / H_, h = r % H_;
                    int bt = b * T_ + t;
                    float2 v;
                    v.x = acc[mi][ni][half*2 + 0];
                    v.y = acc[mi][ni][half*2 + 1];
                    *(float2*)&Ap[((size_t)h*BT + bt)*KVD + cc] = v;
                }
            }
        }
    }
}

// ---------------- generic tf32 GEMM for FFN: A[Mr,Kd] x B[Kd,Nc] + bias ----------------
// block 64x256, Mr multiple of 64 (=448), Nc multiple of 256, Kd multiple of 32.
template<bool RELU>
__global__ __launch_bounds__(256, 2) void gemm_tc(
    const float* __restrict__ A, const float* __restrict__ Bw,
    const float* __restrict__ bias, float* __restrict__ C,
    int Nc, int Kd)
{
    extern __shared__ uint32_t sm[];
    uint32_t* As = sm;                       // [2][64][36]
    uint32_t* Bs = sm + 2*AP_A_WORDS;        // [2][32][264]
    uint32_t sA = (uint32_t)__cvta_generic_to_shared(As);
    uint32_t sB = (uint32_t)__cvta_generic_to_shared(Bs);

    int tid = threadIdx.x;
    int lane = tid & 31, w = tid >> 5;
    int warpM = w & 1, warpN = w >> 1;
    int lg = lane >> 2, lt = lane & 3;
    int colBase = blockIdx.x * 256;
    int rowBase = blockIdx.y * 64;

    float acc[2][8][4];
    #pragma unroll
    for (int mi = 0; mi < 2; mi++)
        #pragma unroll
        for (int ni = 0; ni < 8; ni++)
            #pragma unroll
            for (int q = 0; q < 4; q++) acc[mi][ni][q] = 0.f;

    auto loadA = [&](int kc, int buf) {
        int k0 = kc * 32;
        #pragma unroll
        for (int i = 0; i < 2; i++) {
            int idx = tid + i * 256;
            int r = idx >> 3, c4 = (idx & 7) << 2;
            cpa16(sA + ((buf*AP_A_WORDS + r*SC_A_STRIDE + c4) << 2),
                  A + (size_t)(rowBase + r)*Kd + k0 + c4, 16u);
        }
    };
    auto loadB = [&](int kc, int buf) {
        int k0 = kc * 32;
        #pragma unroll
        for (int i = 0; i < 8; i++) {
            int idx = tid + i * 256;
            int r = idx >> 6, c4 = (idx & 63) << 2;
            cpa16(sB + ((buf*AP_B_WORDS + r*AP_B_STRIDE + c4) << 2),
                  Bw + (size_t)(k0 + r)*Nc + colBase + c4, 16u);
        }
    };

    const int NC = Kd / 32;
    loadA(0, 0); loadB(0, 0); cpa_commit();
    for (int kc = 0; kc < NC; kc++) {
        int cur = kc & 1;
        if (kc + 1 < NC) {
            loadA(kc+1, cur^1); loadB(kc+1, cur^1); cpa_commit();
            cpa_wait1();
        } else {
            cpa_wait0();
        }
        __syncthreads();
        const uint32_t* Ab = As + cur*AP_A_WORDS;
        const uint32_t* Bb = Bs + cur*AP_B_WORDS;
        #pragma unroll
        for (int ks = 0; ks < 4; ks++) {
            int kb = ks * 8;
            uint32_t a[2][4];
            #pragma unroll
            for (int mi = 0; mi < 2; mi++) {
                int r = warpM*32 + mi*16 + lg;
                a[mi][0] = Ab[r*SC_A_STRIDE + kb + lt];
                a[mi][1] = Ab[(r+8)*SC_A_STRIDE + kb + lt];
                a[mi][2] = Ab[r*SC_A_STRIDE + kb + lt + 4];
                a[mi][3] = Ab[(r+8)*SC_A_STRIDE + kb + lt + 4];
            }
            #pragma unroll
            for (int ni = 0; ni < 8; ni++) {
                int n = warpN*64 + ni*8 + lg;
                uint32_t b0 = Bb[(kb + lt)*AP_B_STRIDE + n];
                uint32_t b1 = Bb[(kb + lt + 4)*AP_B_STRIDE + n];
                mma_tf32(acc[0][ni], a[0], b0, b1);
                mma_tf32(acc[1][ni], a[1], b0, b1);
            }
        }
        __syncthreads();
    }

    #pragma unroll
    for (int mi = 0; mi < 2; mi++) {
        #pragma unroll
        for (int ni = 0; ni < 8; ni++) {
            int cc = colBase + warpN*64 + ni*8 + lt*2;
            float bi0 = bias[cc], bi1 = bias[cc + 1];
            #pragma unroll
            for (int half = 0; half < 2; half++) {
                int r = rowBase + warpM*32 + mi*16 + lg + half*8;
                float2 v;
                v.x = acc[mi][ni][half*2 + 0] + bi0;
                v.y = acc[mi][ni][half*2 + 1] + bi1;
                if (RELU) { v.x = fmaxf(v.x, 0.f); v.y = fmaxf(v.y, 0.f); }
                *(float2*)&C[(size_t)r*Nc + cc] = v;
            }
        }
    }
}

// ---------------- attn_out = A' . WV + bV (per head) ----------------
__global__ __launch_bounds__(256) void attnout_kernel(
    const float* __restrict__ Ap, const float* __restrict__ WV,
    const float* __restrict__ bV, float* __restrict__ O)
{
    __shared__ float As[64][33];
    __shared__ float Bs[32][65];
    int h = blockIdx.x;
    int rowBase = blockIdx.y * 64;
    int tid = threadIdx.x;
    int r0 = (tid >> 4) * 4, c0 = (tid & 15) * 4;
    float acc[4][4];
    #pragma unroll
    for (int i = 0; i < 4; i++)
        #pragma unroll
        for (int j = 0; j < 4; j++) acc[i][j] = 0.f;

    const float* Ag = Ap + (size_t)h * BT * KVD;
    for (int k0 = 0; k0 < KVD; k0 += 32) {
        #pragma unroll
        for (int i = 0; i < 2; i++) {
            int idx = tid + i * 256;
            int r = idx >> 3, c4 = (idx & 7) << 2;
            float4 v = *(const float4*)&Ag[(size_t)(rowBase + r)*KVD + k0 + c4];
            As[r][c4+0] = v.x; As[r][c4+1] = v.y; As[r][c4+2] = v.z; As[r][c4+3] = v.w;
        }
        #pragma unroll
        for (int i = 0; i < 2; i++) {
            int idx = tid + i * 256;
            int r = idx >> 4, c4 = (idx & 15) << 2;
            float4 v = *(const float4*)&WV[(size_t)(k0 + r)*QD + h*HD_ + c4];
            Bs[r][c4+0] = v.x; Bs[r][c4+1] = v.y; Bs[r][c4+2] = v.z; Bs[r][c4+3] = v.w;
        }
        __syncthreads();
        #pragma unroll
        for (int kk = 0; kk < 32; kk++) {
            float a[4], bb[4];
            #pragma unroll
            for (int i = 0; i < 4; i++) a[i] = As[r0+i][kk];
            #pragma unroll
            for (int j = 0; j < 4; j++) bb[j] = Bs[kk][c0+j];
            #pragma unroll
            for (int i = 0; i < 4; i++)
                #pragma unroll
                for (int j = 0; j < 4; j++) acc[i][j] += a[i]*bb[j];
        }
        __syncthreads();
    }
    #pragma unroll
    for (int i = 0; i < 4; i++) {
        int bt = rowBase + r0 + i;
        #pragma unroll
        for (int j = 0; j < 4; j++)
            O[(size_t)bt*QD + h*HD_ + c0 + j] = acc[i][j] + bV[h*HD_ + c0 + j];
    }
}

// ---------------- residual add + LayerNorm ----------------
__global__ __launch_bounds__(256) void add_ln_kernel(
    const float* __restrict__ A, const float* __restrict__ Bv,
    const float* __restrict__ g, const float* __restrict__ be,
    float* __restrict__ out)
{
    __shared__ float xs[QD];
    __shared__ float red[256];
    int r = blockIdx.x, tid = threadIdx.x;
    float lsum = 0.f;
    for (int i = tid; i < QD; i += 256) {
        float v = A[(size_t)r*QD + i] + Bv[(size_t)r*QD + i];
        xs[i] = v;
        lsum += v;
    }
    red[tid] = lsum; __syncthreads();
    for (int s = 128; s > 0; s >>= 1) {
        if (tid < s) red[tid] += red[tid + s];
        __syncthreads();
    }
    float mu = red[0] / QD; __syncthreads();
    float lv = 0.f;
    for (int i = tid; i < QD; i += 256) {
        float d0 = xs[i] - mu;
        lv += d0 * d0;
    }
    red[tid] = lv; __syncthreads();
    for (int s = 128; s > 0; s >>= 1) {
        if (tid < s) red[tid] += red[tid + s];
        __syncthreads();
    }
    float inv = rsqrtf(red[0] / QD + EPS_); __syncthreads();
    for (int i = tid; i < QD; i += 256)
        out[(size_t)r*QD + i] = (xs[i] - mu) * inv * g[i] + be[i];
}

// ---------------- launch ----------------
extern "C" void kernel_launch(void* const* d_in, const int* in_sizes, int n_in,
                              void* d_out, int out_size)
{
    const float* X   = (const float*)d_in[0];
    const float* KV  = (const float*)d_in[1];
    const float* WQ  = (const float*)d_in[2];
    const float* bQ  = (const float*)d_in[3];
    const float* WK  = (const float*)d_in[4];
    const float* bK  = (const float*)d_in[5];
    const float* WV  = (const float*)d_in[6];
    const float* bV  = (const float*)d_in[7];
    const float* W1  = (const float*)d_in[8];
    const float* b1  = (const float*)d_in[9];
    const float* W2  = (const float*)d_in[10];
    const float* b2  = (const float*)d_in[11];
    const float* g1  = (const float*)d_in[12];
    const float* be1 = (const float*)d_in[13];
    const float* g2  = (const float*)d_in[14];
    const float* be2 = (const float*)d_in[15];

    float* out   = (float*)d_out;
    float* attnw = out + (size_t)BT*QD;

    float *Qp, *Qtp, *cp, *Sp, *App, *Aop, *X1, *Hm, *Fp;
    cudaGetSymbolAddress((void**)&Qp,  g_Q);
    cudaGetSymbolAddress((void**)&Qtp, g_Qt);
    cudaGetSymbolAddress((void**)&cp,  g_c);
    cudaGetSymbolAddress((void**)&Sp,  g_S);
    cudaGetSymbolAddress((void**)&App, g_Ap);
    cudaGetSymbolAddress((void**)&Aop, g_attn);
    cudaGetSymbolAddress((void**)&X1,  g_x1);
    cudaGetSymbolAddress((void**)&Hm,  g_h);
    cudaGetSymbolAddress((void**)&Fp,  g_ff);

    cudaFuncSetAttribute(scores_kernel, cudaFuncAttributeMaxDynamicSharedMemorySize, SC_SMEM_BYTES);
    cudaFuncSetAttribute(aprime_kernel, cudaFuncAttributeMaxDynamicSharedMemorySize, AP_SMEM_BYTES);
    cudaFuncSetAttribute(gemm_tc<true>,  cudaFuncAttributeMaxDynamicSharedMemorySize, AP_SMEM_BYTES);
    cudaFuncSetAttribute(gemm_tc<false>, cudaFuncAttributeMaxDynamicSharedMemorySize, AP_SMEM_BYTES);

    // Q projection (one GEMM per expert token)
    qproj_kernel<<<dim3(T_, QD/128), 256>>>(X, WQ, bQ, Qp);

    // Qt = Q . WK^T (per head), c = Q . bK
    qt_kernel<<<dim3(H_, BT/64, KVD/64), 256>>>(Qp, WK, Qtp);
    crow_kernel<<<dim3(BT, H_), 32>>>(Qp, bK, cp);

    // scores = Qt . X^T
    scores_kernel<<<dim3(M_/256, 3, B_), 256, SC_SMEM_BYTES>>>(Qtp, KV, Sp);

    // attn_w = softmax((scores + c)/8) -> written directly to output
    softmax_kernel<<<B_*TH, 256>>>(Sp, cp, attnw);

    // A' = P . X
    aprime_kernel<<<dim3(KVD/256, 3, B_), 256, AP_SMEM_BYTES>>>(attnw, KV, App);

    // attn_out = A' . WV + bV
    attnout_kernel<<<dim3(H_, BT/64), 256>>>(App, WV, bV, Aop);

    // x1 = LN(tokens + attn_out)
    add_ln_kernel<<<BT, 256>>>(X, Aop, g1, be1, X1);

    // FFN (tf32 MMA)
    gemm_tc<true ><<<dim3(FF_/256, BT/64), 256, AP_SMEM_BYTES>>>(X1, W1, b1, Hm, FF_, QD);
    gemm_tc<false><<<dim3(QD/256,  BT/64), 256, AP_SMEM_BYTES>>>(Hm, W2, b2, Fp, QD, FF_);

    // out = LN(x1 + ff)
    add_ln_kernel<<<BT, 256>>>(X1, Fp, g2, be2, out);
}

// round 11
// speedup vs baseline: 9.8989x; 1.0875x over previous
#include <cuda_runtime.h>
#include <cstdint>
#include <cstddef>

#define B_   32
#define T_   14
#define M_   2048
#define QD   768
#define KVD  1024
#define H_   12
#define HD_  64
#define FF_  3072
#define BT   (B_*T_)      // 448
#define TH   (T_*H_)      // 168
#define EPS_ 1e-5f

// ---------------- scratch (device globals; no allocation allowed) ----------------
__device__ float g_Q[BT*QD];
__device__ float g_Qt[(size_t)B_*TH*KVD];       // 22 MB
__device__ float g_c[B_*TH];
__device__ float g_S[(size_t)B_*TH*M_];         // 44 MB
__device__ float g_Ap[(size_t)H_*BT*KVD];       // 22 MB
__device__ float g_attn[BT*QD];
__device__ float g_x1[BT*QD];
__device__ float g_h[BT*FF_];
__device__ float g_ff[BT*QD];

// ---------------- helpers ----------------
__device__ __forceinline__ void mma_tf32(float* c, const uint32_t* a, uint32_t b0, uint32_t b1) {
    asm volatile(
        "mma.sync.aligned.m16n8k8.row.col.f32.tf32.tf32.f32 "
        "{%0,%1,%2,%3}, {%4,%5,%6,%7}, {%8,%9}, {%0,%1,%2,%3};\n"
        : "+f"(c[0]), "+f"(c[1]), "+f"(c[2]), "+f"(c[3])
        : "r"(a[0]), "r"(a[1]), "r"(a[2]), "r"(a[3]), "r"(b0), "r"(b1));
}

__device__ __forceinline__ void cpa16(uint32_t saddr, const void* g, uint32_t sz) {
    asm volatile("cp.async.cg.shared.global [%0], [%1], 16, %2;"
                 :: "r"(saddr), "l"(g), "r"(sz));
}
__device__ __forceinline__ void cpa_commit() { asm volatile("cp.async.commit_group;"); }
__device__ __forceinline__ void cpa_wait2()  { asm volatile("cp.async.wait_group 2;"); }
__device__ __forceinline__ void cpa_wait1()  { asm volatile("cp.async.wait_group 1;"); }
__device__ __forceinline__ void cpa_wait0()  { asm volatile("cp.async.wait_group 0;"); }

// ---- old-style gemm (FFN1) smem layout ----
#define SC_A_STRIDE 36
#define AP_B_STRIDE 264
#define AP_A_WORDS  (64*SC_A_STRIDE)
#define AP_B_WORDS  (32*AP_B_STRIDE)
#define AP_SMEM_BYTES ((2*AP_A_WORDS + 2*AP_B_WORDS)*4)    // 86016

// ---- new 96x256, 4-stage layouts ----
#define S2_A_WORDS   (96*36)                 // 3456
#define S2_B_WORDS   (256*36)                // 9216
#define S2_STAGE     (S2_A_WORDS + S2_B_WORDS)
#define S2_SMEM_BYTES (4*S2_STAGE*4)         // 202752

#define A2_A_WORDS   (96*36)
#define A2_B_WORDS   (32*AP_B_STRIDE)        // 8448
#define A2_STAGE     (A2_A_WORDS + A2_B_WORDS)
#define A2_SMEM_BYTES (4*A2_STAGE*4)         // 190464

// ---------------- Q projection: one GEMM per expert-token t ----------------
__global__ __launch_bounds__(256) void qproj_kernel(
    const float* __restrict__ X, const float* __restrict__ WQ,
    const float* __restrict__ bQ, float* __restrict__ Q)
{
    int t = blockIdx.x;
    int colBase = blockIdx.y * 128;
    __shared__ float As[32][33];
    __shared__ float Bs[32][132];
    int tid = threadIdx.x;
    int r0 = (tid >> 5) * 4;
    int c0 = (tid & 31) * 4;
    float acc[4][4];
    #pragma unroll
    for (int i = 0; i < 4; i++)
        #pragma unroll
        for (int j = 0; j < 4; j++) acc[i][j] = 0.f;

    const float* Wt = WQ + (size_t)t * QD * QD;
    for (int k0 = 0; k0 < QD; k0 += 32) {
        {
            int r = tid >> 3, c4 = (tid & 7) << 2;
            float4 v = *(const float4*)&X[(size_t)(r*T_ + t)*QD + k0 + c4];
            As[r][c4+0] = v.x; As[r][c4+1] = v.y; As[r][c4+2] = v.z; As[r][c4+3] = v.w;
        }
        #pragma unroll
        for (int i = 0; i < 4; i++) {
            int idx = tid + i * 256;
            int r = idx >> 5, c4 = (idx & 31) << 2;
            float4 v = *(const float4*)&Wt[(size_t)(k0 + r)*QD + colBase + c4];
            Bs[r][c4+0] = v.x; Bs[r][c4+1] = v.y; Bs[r][c4+2] = v.z; Bs[r][c4+3] = v.w;
        }
        __syncthreads();
        #pragma unroll
        for (int kk = 0; kk < 32; kk++) {
            float a[4];
            #pragma unroll
            for (int i = 0; i < 4; i++) a[i] = As[r0+i][kk];
            float4 b4 = *(float4*)&Bs[kk][c0];
            float bb[4] = {b4.x, b4.y, b4.z, b4.w};
            #pragma unroll
            for (int i = 0; i < 4; i++)
                #pragma unroll
                for (int j = 0; j < 4; j++) acc[i][j] += a[i]*bb[j];
        }
        __syncthreads();
    }
    #pragma unroll
    for (int i = 0; i < 4; i++) {
        int bt = (r0 + i)*T_ + t;
        #pragma unroll
        for (int j = 0; j < 4; j++) {
            int c = colBase + c0 + j;
            Q[(size_t)bt*QD + c] = acc[i][j] + bQ[t*QD + c];
        }
    }
}

// ---------------- Qt[b,t,h,e] = sum_d Q[bt, h*64+d] * WK[e, h*64+d] ----------------
__global__ __launch_bounds__(256) void qt_kernel(
    const float* __restrict__ Q, const float* __restrict__ WK,
    float* __restrict__ Qt)
{
    int h  = blockIdx.x;
    int rt = blockIdx.y;
    int et = blockIdx.z;
    __shared__ float Asq[64][65];
    __shared__ float Bsq[64][65];
    int tid = threadIdx.x;
    #pragma unroll
    for (int it = 0; it < 4; it++) {
        int id = tid + it * 256;
        int r = id >> 4, c4 = (id & 15) << 2;
        float4 v = *(const float4*)&Q[(size_t)(rt*64 + r)*QD + h*HD_ + c4];
        Asq[r][c4+0] = v.x; Asq[r][c4+1] = v.y; Asq[r][c4+2] = v.z; Asq[r][c4+3] = v.w;
        float4 w = *(const float4*)&WK[(size_t)(et*64 + r)*QD + h*HD_ + c4];
        Bsq[r][c4+0] = w.x; Bsq[r][c4+1] = w.y; Bsq[r][c4+2] = w.z; Bsq[r][c4+3] = w.w;
    }
    __syncthreads();
    int r0 = (tid >> 4) * 4, e0 = (tid & 15) * 4;
    float acc[4][4];
    #pragma unroll
    for (int i = 0; i < 4; i++)
        #pragma unroll
        for (int j = 0; j < 4; j++) acc[i][j] = 0.f;
    #pragma unroll 8
    for (int d = 0; d < 64; d++) {
        float a[4], b[4];
        #pragma unroll
        for (int i = 0; i < 4; i++) a[i] = Asq[r0+i][d];
        #pragma unroll
        for (int j = 0; j < 4; j++) b[j] = Bsq[e0+j][d];
        #pragma unroll
        for (int i = 0; i < 4; i++)
            #pragma unroll
            for (int j = 0; j < 4; j++) acc[i][j] += a[i]*b[j];
    }
    #pragma unroll
    for (int i = 0; i < 4; i++) {
        int bt = rt*64 + r0 + i;
        int b  = bt / T_, t = bt % T_;
        float* dst = Qt + ((size_t)(b*TH + t*H_ + h))*KVD + et*64 + e0;
        #pragma unroll
        for (int j = 0; j < 4; j++) dst[j] = acc[i][j];
    }
}

// ---------------- c row constant ----------------
__global__ __launch_bounds__(32) void crow_kernel(
    const float* __restrict__ Q, const float* __restrict__ bK, float* __restrict__ c)
{
    int bt = blockIdx.x, h = blockIdx.y;
    int lane = threadIdx.x;
    float s = Q[(size_t)bt*QD + h*HD_ + lane]      * bK[h*HD_ + lane]
            + Q[(size_t)bt*QD + h*HD_ + 32 + lane] * bK[h*HD_ + 32 + lane];
    #pragma unroll
    for (int o = 16; o > 0; o >>= 1) s += __shfl_down_sync(0xffffffffu, s, o);
    if (lane == 0) {
        int b = bt / T_, t = bt % T_;
        c[b*TH + t*H_ + h] = s;
    }
}

// ---------------- scores: S[b] = Qt[b] (168x1024) . X[b]^T -> [168, 2048] ----------------
// block 96x256, warp tile 48x64 (2M x 4N warps), 4-stage cp.async, 1 block/SM.
// grid (M_/256, 2, B_)
__global__ __launch_bounds__(256, 1) void scores_kernel(
    const float* __restrict__ Qt, const float* __restrict__ X,
    float* __restrict__ S)
{
    extern __shared__ uint32_t sm[];
    uint32_t sBase = (uint32_t)__cvta_generic_to_shared(sm);

    int tid = threadIdx.x;
    int lane = tid & 31, w = tid >> 5;
    int warpM = w & 1, warpN = w >> 1;
    int lg = lane >> 2, lt = lane & 3;
    int colBase = blockIdx.x * 256;
    int rowBase = blockIdx.y * 96;
    int b = blockIdx.z;

    const float* Ag = Qt + (size_t)b * TH * KVD;
    const float* Bg = X  + (size_t)b * M_ * KVD;

    float acc[3][8][4];
    #pragma unroll
    for (int mi = 0; mi < 3; mi++)
        #pragma unroll
        for (int ni = 0; ni < 8; ni++)
            #pragma unroll
            for (int q = 0; q < 4; q++) acc[mi][ni][q] = 0.f;

    auto loadStage = [&](int kc, int buf) {
        int k0 = kc * 32;
        uint32_t base = sBase + (uint32_t)(buf * S2_STAGE) * 4u;
        // A: 96x32 = 768 float4 -> 3 per thread
        #pragma unroll
        for (int i = 0; i < 3; i++) {
            int idx = tid + i * 256;
            int r = idx >> 3, c4 = (idx & 7) << 2;
            int gr = rowBase + r;
            int grc = gr < TH ? gr : TH - 1;
            uint32_t sz = gr < TH ? 16u : 0u;
            cpa16(base + ((r*36 + c4) << 2),
                  Ag + (size_t)grc*KVD + k0 + c4, sz);
        }
        // B: 256x32 = 2048 float4 -> 8 per thread
        uint32_t bb = base + (uint32_t)S2_A_WORDS * 4u;
        #pragma unroll
        for (int i = 0; i < 8; i++) {
            int idx = tid + i * 256;
            int r = idx >> 3, c4 = (idx & 7) << 2;
            cpa16(bb + ((r*36 + c4) << 2),
                  Bg + (size_t)(colBase + r)*KVD + k0 + c4, 16u);
        }
        cpa_commit();
    };

    const int NC = KVD / 32;   // 32
    loadStage(0, 0); loadStage(1, 1); loadStage(2, 2);
    for (int kc = 0; kc < NC; kc++) {
        if (kc < NC-2) cpa_wait2(); else if (kc == NC-2) cpa_wait1(); else cpa_wait0();
        __syncthreads();
        if (kc + 3 < NC) loadStage(kc+3, (kc+3)&3);
        const uint32_t* Ab = sm + (kc&3)*S2_STAGE;
        const uint32_t* Bb = Ab + S2_A_WORDS;
        #pragma unroll
        for (int ks = 0; ks < 4; ks++) {
            int kb = ks * 8;
            uint32_t a[3][4];
            #pragma unroll
            for (int mi = 0; mi < 3; mi++) {
                int r = warpM*48 + mi*16 + lg;
                a[mi][0] = Ab[r*36 + kb + lt];
                a[mi][1] = Ab[(r+8)*36 + kb + lt];
                a[mi][2] = Ab[r*36 + kb + lt + 4];
                a[mi][3] = Ab[(r+8)*36 + kb + lt + 4];
            }
            #pragma unroll
            for (int ni = 0; ni < 8; ni++) {
                int n = warpN*64 + ni*8 + lg;
                uint32_t b0 = Bb[n*36 + kb + lt];
                uint32_t b1 = Bb[n*36 + kb + lt + 4];
                mma_tf32(acc[0][ni], a[0], b0, b1);
                mma_tf32(acc[1][ni], a[1], b0, b1);
                mma_tf32(acc[2][ni], a[2], b0, b1);
            }
        }
        __syncthreads();
    }

    float* Sg = S + (size_t)b * TH * M_;
    #pragma unroll
    for (int mi = 0; mi < 3; mi++) {
        #pragma unroll
        for (int ni = 0; ni < 8; ni++) {
            int r = rowBase + warpM*48 + mi*16 + lg;
            int cc = colBase + warpN*64 + ni*8 + lt*2;
            if (r < TH) {
                float2 v; v.x = acc[mi][ni][0]; v.y = acc[mi][ni][1];
                *(float2*)&Sg[(size_t)r*M_ + cc] = v;
            }
            if (r + 8 < TH) {
                float2 v; v.x = acc[mi][ni][2]; v.y = acc[mi][ni][3];
                *(float2*)&Sg[(size_t)(r+8)*M_ + cc] = v;
            }
        }
    }
}

// ---------------- softmax ----------------
__global__ __launch_bounds__(256) void softmax_kernel(
    const float* __restrict__ S, const float* __restrict__ c,
    float* __restrict__ P)
{
    __shared__ float red[256];
    int row = blockIdx.x, tid = threadIdx.x;
    const float* s = S + (size_t)row * M_;
    float*       p = P + (size_t)row * M_;
    float cv = c[row];
    float vals[8];
    float mx = -1e30f;
    #pragma unroll
    for (int i = 0; i < 8; i++) {
        float v = (s[tid + i*256] + cv) * 0.125f;
        vals[i] = v;
        mx = fmaxf(mx, v);
    }
    red[tid] = mx; __syncthreads();
    for (int o = 128; o > 0; o >>= 1) {
        if (tid < o) red[tid] = fmaxf(red[tid], red[tid + o]);
        __syncthreads();
    }
    mx = red[0]; __syncthreads();
    float sum = 0.f;
    #pragma unroll
    for (int i = 0; i < 8; i++) {
        vals[i] = __expf(vals[i] - mx);
        sum += vals[i];
    }
    red[tid] = sum; __syncthreads();
    for (int o = 128; o > 0; o >>= 1) {
        if (tid < o) red[tid] += red[tid + o];
        __syncthreads();
    }
    float inv = 1.f / red[0];
    #pragma unroll
    for (int i = 0; i < 8; i++) p[tid + i*256] = vals[i] * inv;
}

// ---------------- A' = P[b] (168x2048) . X[b] (2048x1024) -> [h][bt][e] ----------------
// block 96x256, warp tile 48x64, 4-stage cp.async, 1 block/SM. grid (KVD/256, 2, B_)
__global__ __launch_bounds__(256, 1) void aprime_kernel(
    const float* __restrict__ P, const float* __restrict__ X,
    float* __restrict__ Ap)
{
    extern __shared__ uint32_t sm[];
    uint32_t sBase = (uint32_t)__cvta_generic_to_shared(sm);

    int tid = threadIdx.x;
    int lane = tid & 31, w = tid >> 5;
    int warpM = w & 1, warpN = w >> 1;
    int lg = lane >> 2, lt = lane & 3;
    int colBase = blockIdx.x * 256;
    int rowBase = blockIdx.y * 96;
    int b = blockIdx.z;

    const float* Ag = P + (size_t)b * TH * M_;
    const float* Bg = X + (size_t)b * M_ * KVD;

    float acc[3][8][4];
    #pragma unroll
    for (int mi = 0; mi < 3; mi++)
        #pragma unroll
        for (int ni = 0; ni < 8; ni++)
            #pragma unroll
            for (int q = 0; q < 4; q++) acc[mi][ni][q] = 0.f;

    auto loadStage = [&](int kc, int buf) {
        int k0 = kc * 32;
        uint32_t base = sBase + (uint32_t)(buf * A2_STAGE) * 4u;
        #pragma unroll
        for (int i = 0; i < 3; i++) {
            int idx = tid + i * 256;
            int r = idx >> 3, c4 = (idx & 7) << 2;
            int gr = rowBase + r;
            int grc = gr < TH ? gr : TH - 1;
            uint32_t sz = gr < TH ? 16u : 0u;
            cpa16(base + ((r*36 + c4) << 2),
                  Ag + (size_t)grc*M_ + k0 + c4, sz);
        }
        uint32_t bb = base + (uint32_t)A2_A_WORDS * 4u;
        #pragma unroll
        for (int i = 0; i < 8; i++) {
            int idx = tid + i * 256;
            int r = idx >> 6, c4 = (idx & 63) << 2;
            cpa16(bb + ((r*AP_B_STRIDE + c4) << 2),
                  Bg + (size_t)(k0 + r)*KVD + colBase + c4, 16u);
        }
        cpa_commit();
    };

    const int NC = M_ / 32;   // 64
    loadStage(0, 0); loadStage(1, 1); loadStage(2, 2);
    for (int kc = 0; kc < NC; kc++) {
        if (kc < NC-2) cpa_wait2(); else if (kc == NC-2) cpa_wait1(); else cpa_wait0();
        __syncthreads();
        if (kc + 3 < NC) loadStage(kc+3, (kc+3)&3);
        const uint32_t* Ab = sm + (kc&3)*A2_STAGE;
        const uint32_t* Bb = Ab + A2_A_WORDS;
        #pragma unroll
        for (int ks = 0; ks < 4; ks++) {
            int kb = ks * 8;
            uint32_t a[3][4];
            #pragma unroll
            for (int mi = 0; mi < 3; mi++) {
                int r = warpM*48 + mi*16 + lg;
                a[mi][0] = Ab[r*36 + kb + lt];
                a[mi][1] = Ab[(r+8)*36 + kb + lt];
                a[mi][2] = Ab[r*36 + kb + lt + 4];
                a[mi][3] = Ab[(r+8)*36 + kb + lt + 4];
            }
            #pragma unroll
            for (int ni = 0; ni < 8; ni++) {
                int n = warpN*64 + ni*8 + lg;
                uint32_t b0 = Bb[(kb + lt)*AP_B_STRIDE + n];
                uint32_t b1 = Bb[(kb + lt + 4)*AP_B_STRIDE + n];
                mma_tf32(acc[0][ni], a[0], b0, b1);
                mma_tf32(acc[1][ni], a[1], b0, b1);
                mma_tf32(acc[2][ni], a[2], b0, b1);
            }
        }
        __syncthreads();
    }

    #pragma unroll
    for (int mi = 0; mi < 3; mi++) {
        #pragma unroll
        for (int ni = 0; ni < 8; ni++) {
            int cc = colBase + warpN*64 + ni*8 + lt*2;
            #pragma unroll
            for (int half = 0; half < 2; half++) {
                int r = rowBase + warpM*48 + mi*16 + lg + half*8;
                if (r < TH) {
                    int t = r / H_, h = r % H_;
                    int bt = b * T_ + t;
                    float2 v;
                    v.x = acc[mi][ni][half*2 + 0];
                    v.y = acc[mi][ni][half*2 + 1];
                    *(float2*)&Ap[((size_t)h*BT + bt)*KVD + cc] = v;
                }
            }
        }
    }
}

// ---------------- tf32 GEMM (FFN1): 64x256, 2-stage, 2 blk/SM ----------------
template<bool RELU>
__global__ __launch_bounds__(256, 2) void gemm_tc(
    const float* __restrict__ A, const float* __restrict__ Bw,
    const float* __restrict__ bias, float* __restrict__ C,
    int Nc, int Kd)
{
    extern __shared__ uint32_t sm[];
    uint32_t* As = sm;
    uint32_t* Bs = sm + 2*AP_A_WORDS;
    uint32_t sA = (uint32_t)__cvta_generic_to_shared(As);
    uint32_t sB = (uint32_t)__cvta_generic_to_shared(Bs);

    int tid = threadIdx.x;
    int lane = tid & 31, w = tid >> 5;
    int warpM = w & 1, warpN = w >> 1;
    int lg = lane >> 2, lt = lane & 3;
    int colBase = blockIdx.x * 256;
    int rowBase = blockIdx.y * 64;

    float acc[2][8][4];
    #pragma unroll
    for (int mi = 0; mi < 2; mi++)
        #pragma unroll
        for (int ni = 0; ni < 8; ni++)
            #pragma unroll
            for (int q = 0; q < 4; q++) acc[mi][ni][q] = 0.f;

    auto loadA = [&](int kc, int buf) {
        int k0 = kc * 32;
        #pragma unroll
        for (int i = 0; i < 2; i++) {
            int idx = tid + i * 256;
            int r = idx >> 3, c4 = (idx & 7) << 2;
            cpa16(sA + ((buf*AP_A_WORDS + r*SC_A_STRIDE + c4) << 2),
                  A + (size_t)(rowBase + r)*Kd + k0 + c4, 16u);
        }
    };
    auto loadB = [&](int kc, int buf) {
        int k0 = kc * 32;
        #pragma unroll
        for (int i = 0; i < 8; i++) {
            int idx = tid + i * 256;
            int r = idx >> 6, c4 = (idx & 63) << 2;
            cpa16(sB + ((buf*AP_B_WORDS + r*AP_B_STRIDE + c4) << 2),
                  Bw + (size_t)(k0 + r)*Nc + colBase + c4, 16u);
        }
    };

    const int NC = Kd / 32;
    loadA(0, 0); loadB(0, 0); cpa_commit();
    for (int kc = 0; kc < NC; kc++) {
        int cur = kc & 1;
        if (kc + 1 < NC) {
            loadA(kc+1, cur^1); loadB(kc+1, cur^1); cpa_commit();
            cpa_wait1();
        } else {
            cpa_wait0();
        }
        __syncthreads();
        const uint32_t* Ab = As + cur*AP_A_WORDS;
        const uint32_t* Bb = Bs + cur*AP_B_WORDS;
        #pragma unroll
        for (int ks = 0; ks < 4; ks++) {
            int kb = ks * 8;
            uint32_t a[2][4];
            #pragma unroll
            for (int mi = 0; mi < 2; mi++) {
                int r = warpM*32 + mi*16 + lg;
                a[mi][0] = Ab[r*SC_A_STRIDE + kb + lt];
                a[mi][1] = Ab[(r+8)*SC_A_STRIDE + kb + lt];
                a[mi][2] = Ab[r*SC_A_STRIDE + kb + lt + 4];
                a[mi][3] = Ab[(r+8)*SC_A_STRIDE + kb + lt + 4];
            }
            #pragma unroll
            for (int ni = 0; ni < 8; ni++) {
                int n = warpN*64 + ni*8 + lg;
                uint32_t b0 = Bb[(kb + lt)*AP_B_STRIDE + n];
                uint32_t b1 = Bb[(kb + lt + 4)*AP_B_STRIDE + n];
                mma_tf32(acc[0][ni], a[0], b0, b1);
                mma_tf32(acc[1][ni], a[1], b0, b1);
            }
        }
        __syncthreads();
    }

    #pragma unroll
    for (int mi = 0; mi < 2; mi++) {
        #pragma unroll
        for (int ni = 0; ni < 8; ni++) {
            int cc = colBase + warpN*64 + ni*8 + lt*2;
            float bi0 = bias[cc], bi1 = bias[cc + 1];
            #pragma unroll
            for (int half = 0; half < 2; half++) {
                int r = rowBase + warpM*32 + mi*16 + lg + half*8;
                float2 v;
                v.x = acc[mi][ni][half*2 + 0] + bi0;
                v.y = acc[mi][ni][half*2 + 1] + bi1;
                if (RELU) { v.x = fmaxf(v.x, 0.f); v.y = fmaxf(v.y, 0.f); }
                *(float2*)&C[(size_t)r*Nc + cc] = v;
            }
        }
    }
}

// ---------------- tf32 GEMM, N-tile 64 (FFN2 — needs block parallelism) ----------------
// block 64x64, warps 2M x 4N, warp tile 32x16.
__global__ __launch_bounds__(256) void gemm_tc_n64(
    const float* __restrict__ A, const float* __restrict__ Bw,
    const float* __restrict__ bias, float* __restrict__ C,
    int Nc, int Kd)
{
    __shared__ uint32_t As[2][64][36];
    __shared__ uint32_t Bs[2][32][72];
    uint32_t sA = (uint32_t)__cvta_generic_to_shared(&As[0][0][0]);
    uint32_t sB = (uint32_t)__cvta_generic_to_shared(&Bs[0][0][0]);

    int tid = threadIdx.x;
    int lane = tid & 31, w = tid >> 5;
    int warpM = w & 1, warpN = w >> 1;
    int lg = lane >> 2, lt = lane & 3;
    int colBase = blockIdx.x * 64;
    int rowBase = blockIdx.y * 64;

    float acc[2][2][4];
    #pragma unroll
    for (int mi = 0; mi < 2; mi++)
        #pragma unroll
        for (int ni = 0; ni < 2; ni++)
            #pragma unroll
            for (int q = 0; q < 4; q++) acc[mi][ni][q] = 0.f;

    auto loadStage = [&](int kc, int buf) {
        int k0 = kc * 32;
        // A 64x32 = 512 f4 -> 2/thread
        #pragma unroll
        for (int i = 0; i < 2; i++) {
            int idx = tid + i * 256;
            int r = idx >> 3, c4 = (idx & 7) << 2;
            cpa16(sA + ((buf*64*36 + r*36 + c4) << 2),
                  A + (size_t)(rowBase + r)*Kd + k0 + c4, 16u);
        }
        // B 32x64 = 512 f4 -> 2/thread
        #pragma unroll
        for (int i = 0; i < 2; i++) {
            int idx = tid + i * 256;
            int r = idx >> 4, c4 = (idx & 15) << 2;
            cpa16(sB + ((buf*32*72 + r*72 + c4) << 2),
                  Bw + (size_t)(k0 + r)*Nc + colBase + c4, 16u);
        }
        cpa_commit();
    };

    const int NC = Kd / 32;
    loadStage(0, 0);
    for (int kc = 0; kc < NC; kc++) {
        int cur = kc & 1;
        if (kc + 1 < NC) { loadStage(kc+1, cur^1); cpa_wait1(); }
        else             { cpa_wait0(); }
        __syncthreads();
        #pragma unroll
        for (int ks = 0; ks < 4; ks++) {
            int kb = ks * 8;
            uint32_t a[2][4];
            #pragma unroll
            for (int mi = 0; mi < 2; mi++) {
                int r = warpM*32 + mi*16 + lg;
                a[mi][0] = As[cur][r][kb + lt];
                a[mi][1] = As[cur][r+8][kb + lt];
                a[mi][2] = As[cur][r][kb + lt + 4];
                a[mi][3] = As[cur][r+8][kb + lt + 4];
            }
            #pragma unroll
            for (int ni = 0; ni < 2; ni++) {
                int n = warpN*16 + ni*8 + lg;
                uint32_t b0 = Bs[cur][kb + lt][n];
                uint32_t b1 = Bs[cur][kb + lt + 4][n];
                mma_tf32(acc[0][ni], a[0], b0, b1);
                mma_tf32(acc[1][ni], a[1], b0, b1);
            }
        }
        __syncthreads();
    }

    #pragma unroll
    for (int mi = 0; mi < 2; mi++) {
        #pragma unroll
        for (int ni = 0; ni < 2; ni++) {
            int cc = colBase + warpN*16 + ni*8 + lt*2;
            float bi0 = bias[cc], bi1 = bias[cc + 1];
            #pragma unroll
            for (int half = 0; half < 2; half++) {
                int r = rowBase + warpM*32 + mi*16 + lg + half*8;
                float2 v;
                v.x = acc[mi][ni][half*2 + 0] + bi0;
                v.y = acc[mi][ni][half*2 + 1] + bi1;
                *(float2*)&C[(size_t)r*Nc + cc] = v;
            }
        }
    }
}

// ---------------- attn_out = A' . WV + bV (per head) ----------------
__global__ __launch_bounds__(256) void attnout_kernel(
    const float* __restrict__ Ap, const float* __restrict__ WV,
    const float* __restrict__ bV, float* __restrict__ O)
{
    __shared__ float As[64][33];
    __shared__ float Bs[32][65];
    int h = blockIdx.x;
    int rowBase = blockIdx.y * 64;
    int tid = threadIdx.x;
    int r0 = (tid >> 4) * 4, c0 = (tid & 15) * 4;
    float acc[4][4];
    #pragma unroll
    for (int i = 0; i < 4; i++)
        #pragma unroll
        for (int j = 0; j < 4; j++) acc[i][j] = 0.f;

    const float* Ag = Ap + (size_t)h * BT * KVD;
    for (int k0 = 0; k0 < KVD; k0 += 32) {
        #pragma unroll
        for (int i = 0; i < 2; i++) {
            int idx = tid + i * 256;
            int r = idx >> 3, c4 = (idx & 7) << 2;
            float4 v = *(const float4*)&Ag[(size_t)(rowBase + r)*KVD + k0 + c4];
            As[r][c4+0] = v.x; As[r][c4+1] = v.y; As[r][c4+2] = v.z; As[r][c4+3] = v.w;
        }
        #pragma unroll
        for (int i = 0; i < 2; i++) {
            int idx = tid + i * 256;
            int r = idx >> 4, c4 = (idx & 15) << 2;
            float4 v = *(const float4*)&WV[(size_t)(k0 + r)*QD + h*HD_ + c4];
            Bs[r][c4+0] = v.x; Bs[r][c4+1] = v.y; Bs[r][c4+2] = v.z; Bs[r][c4+3] = v.w;
        }
        __syncthreads();
        #pragma unroll
        for (int kk = 0; kk < 32; kk++) {
            float a[4], bb[4];
            #pragma unroll
            for (int i = 0; i < 4; i++) a[i] = As[r0+i][kk];
            #pragma unroll
            for (int j = 0; j < 4; j++) bb[j] = Bs[kk][c0+j];
            #pragma unroll
            for (int i = 0; i < 4; i++)
                #pragma unroll
                for (int j = 0; j < 4; j++) acc[i][j] += a[i]*bb[j];
        }
        __syncthreads();
    }
    #pragma unroll
    for (int i = 0; i < 4; i++) {
        int bt = rowBase + r0 + i;
        #pragma unroll
        for (int j = 0; j < 4; j++)
            O[(size_t)bt*QD + h*HD_ + c0 + j] = acc[i][j] + bV[h*HD_ + c0 + j];
    }
}

// ---------------- residual add + LayerNorm ----------------
__global__ __launch_bounds__(256) void add_ln_kernel(
    const float* __restrict__ A, const float* __restrict__ Bv,
    const float* __restrict__ g, const float* __restrict__ be,
    float* __restrict__ out)
{
    __shared__ float xs[QD];
    __shared__ float red[256];
    int r = blockIdx.x, tid = threadIdx.x;
    float lsum = 0.f;
    for (int i = tid; i < QD; i += 256) {
        float v = A[(size_t)r*QD + i] + Bv[(size_t)r*QD + i];
        xs[i] = v;
        lsum += v;
    }
    red[tid] = lsum; __syncthreads();
    for (int s = 128; s > 0; s >>= 1) {
        if (tid < s) red[tid] += red[tid + s];
        __syncthreads();
    }
    float mu = red[0] / QD; __syncthreads();
    float lv = 0.f;
    for (int i = tid; i < QD; i += 256) {
        float d0 = xs[i] - mu;
        lv += d0 * d0;
    }
    red[tid] = lv; __syncthreads();
    for (int s = 128; s > 0; s >>= 1) {
        if (tid < s) red[tid] += red[tid + s];
        __syncthreads();
    }
    float inv = rsqrtf(red[0] / QD + EPS_); __syncthreads();
    for (int i = tid; i < QD; i += 256)
        out[(size_t)r*QD + i] = (xs[i] - mu) * inv * g[i] + be[i];
}

// ---------------- launch ----------------
extern "C" void kernel_launch(void* const* d_in, const int* in_sizes, int n_in,
                              void* d_out, int out_size)
{
    const float* X   = (const float*)d_in[0];
    const float* KV  = (const float*)d_in[1];
    const float* WQ  = (const float*)d_in[2];
    const float* bQ  = (const float*)d_in[3];
    const float* WK  = (const float*)d_in[4];
    const float* bK  = (const float*)d_in[5];
    const float* WV  = (const float*)d_in[6];
    const float* bV  = (const float*)d_in[7];
    const float* W1  = (const float*)d_in[8];
    const float* b1  = (const float*)d_in[9];
    const float* W2  = (const float*)d_in[10];
    const float* b2  = (const float*)d_in[11];
    const float* g1  = (const float*)d_in[12];
    const float* be1 = (const float*)d_in[13];
    const float* g2  = (const float*)d_in[14];
    const float* be2 = (const float*)d_in[15];

    float* out   = (float*)d_out;
    float* attnw = out + (size_t)BT*QD;

    float *Qp, *Qtp, *cp, *Sp, *App, *Aop, *X1, *Hm, *Fp;
    cudaGetSymbolAddress((void**)&Qp,  g_Q);
    cudaGetSymbolAddress((void**)&Qtp, g_Qt);
    cudaGetSymbolAddress((void**)&cp,  g_c);
    cudaGetSymbolAddress((void**)&Sp,  g_S);
    cudaGetSymbolAddress((void**)&App, g_Ap);
    cudaGetSymbolAddress((void**)&Aop, g_attn);
    cudaGetSymbolAddress((void**)&X1,  g_x1);
    cudaGetSymbolAddress((void**)&Hm,  g_h);
    cudaGetSymbolAddress((void**)&Fp,  g_ff);

    cudaFuncSetAttribute(scores_kernel, cudaFuncAttributeMaxDynamicSharedMemorySize, S2_SMEM_BYTES);
    cudaFuncSetAttribute(aprime_kernel, cudaFuncAttributeMaxDynamicSharedMemorySize, A2_SMEM_BYTES);
    cudaFuncSetAttribute(gemm_tc<true>,  cudaFuncAttributeMaxDynamicSharedMemorySize, AP_SMEM_BYTES);

    // Q projection (one GEMM per expert token)
    qproj_kernel<<<dim3(T_, QD/128), 256>>>(X, WQ, bQ, Qp);

    // Qt = Q . WK^T (per head), c = Q . bK
    qt_kernel<<<dim3(H_, BT/64, KVD/64), 256>>>(Qp, WK, Qtp);
    crow_kernel<<<dim3(BT, H_), 32>>>(Qp, bK, cp);

    // scores = Qt . X^T  (96x256 tiles, 4-stage)
    scores_kernel<<<dim3(M_/256, 2, B_), 256, S2_SMEM_BYTES>>>(Qtp, KV, Sp);

    // attn_w = softmax((scores + c)/8) -> written directly to output
    softmax_kernel<<<B_*TH, 256>>>(Sp, cp, attnw);

    // A' = P . X  (96x256 tiles, 4-stage)
    aprime_kernel<<<dim3(KVD/256, 2, B_), 256, A2_SMEM_BYTES>>>(attnw, KV, App);

    // attn_out = A' . WV + bV
    attnout_kernel<<<dim3(H_, BT/64), 256>>>(App, WV, bV, Aop);

    // x1 = LN(tokens + attn_out)
    add_ln_kernel<<<BT, 256>>>(X, Aop, g1, be1, X1);

    // FFN
    gemm_tc<true ><<<dim3(FF_/256, BT/64), 256, AP_SMEM_BYTES>>>(X1, W1, b1, Hm, FF_, QD);
    gemm_tc_n64  <<<dim3(QD/64,   BT/64), 256>>>(Hm, W2, b2, Fp, QD, FF_);

    // out = LN(x1 + ff)
    add_ln_kernel<<<BT, 256>>>(X1, Fp, g2, be2, out);
}